// round 11
// baseline (speedup 1.0000x reference)
#include <cuda_runtime.h>
#include <cuda_bf16.h>
#include <math.h>
#include <stdint.h>

#define Hh 128
#define Ww 128
#define HW 16384
#define CC 256

// ---------------- scratch (static __device__, no allocs) ----------------
__device__ float g_b1[CC * HW];
__device__ float g_b2[CC * HW];
__device__ float g_head[9 * 16 * HW];
__device__ float g_head2[9 * 16 * HW];
__device__ float g_wt_small[81920];
__device__ unsigned char g_wpack[333 * 65536];
// pair tensors: u32 word = (bf16 ch 2m) | (bf16 ch 2m+1 << 16), index m*HW + p
__device__ uint32_t g_p0h[128 * HW];
__device__ uint32_t g_p0l[128 * HW];
__device__ uint32_t g_p1h[128 * HW];
__device__ uint32_t g_p1l[128 * HW];
__device__ uint32_t g_p2h[128 * HW];
__device__ uint32_t g_p2l[128 * HW];
__device__ uint32_t g_p3h[128 * HW];
__device__ uint32_t g_p3l[128 * HW];
__device__ uint32_t g_pdh[16 * HW];
__device__ uint32_t g_pdl[16 * HW];

__constant__ int c_ring[8] = {0, 1, 2, 5, 8, 7, 6, 3};

struct WPtrs {
    const float* w[9];
};

// ---------------- helpers ----------------
__device__ __forceinline__ uint32_t smem_u32(const void* p) {
    uint32_t a;
    asm("{ .reg .u64 t; cvta.to.shared.u64 t, %1; cvt.u32.u64 %0, t; }" : "=r"(a) : "l"(p));
    return a;
}
__device__ __forceinline__ void ldm4(uint32_t* r, uint32_t addr) {
    asm volatile("ldmatrix.sync.aligned.m8n8.x4.shared.b16 {%0,%1,%2,%3}, [%4];"
                 : "=r"(r[0]), "=r"(r[1]), "=r"(r[2]), "=r"(r[3]) : "r"(addr));
}
__device__ __forceinline__ void mma_bf16(float* c, const uint32_t* a, uint32_t b0, uint32_t b1) {
    asm volatile(
        "mma.sync.aligned.m16n8k16.row.col.f32.bf16.bf16.f32 "
        "{%0,%1,%2,%3}, {%4,%5,%6,%7}, {%8,%9}, {%0,%1,%2,%3};"
        : "+f"(c[0]), "+f"(c[1]), "+f"(c[2]), "+f"(c[3])
        : "r"(a[0]), "r"(a[1]), "r"(a[2]), "r"(a[3]), "r"(b0), "r"(b1));
}
__device__ __forceinline__ unsigned short bf16u(float v) {
    __nv_bfloat16 b = __float2bfloat16(v);
    return *(unsigned short*)&b;
}
__device__ __forceinline__ float ubf(unsigned short u) {
    __nv_bfloat16 b = *(__nv_bfloat16*)&u;
    return __bfloat162float(b);
}
__device__ __forceinline__ float half_of(uint32_t w, int hi) {
    return ubf((unsigned short)(hi ? (w >> 16) : (w & 0xFFFF)));
}
__device__ __forceinline__ void cp_async_tile(uint32_t dst, const unsigned char* src, int tid) {
#pragma unroll
    for (int i = 0; i < 16; i++) {
        asm volatile("cp.async.cg.shared.global [%0], [%1], 16;"
                     :: "r"(dst + (uint32_t)(tid + i * 256) * 16),
                        "l"(src + (size_t)(tid + i * 256) * 16) : "memory");
    }
    asm volatile("cp.async.commit_group;" ::: "memory");
}
__device__ __forceinline__ void cp_async_wait0() {
    asm volatile("cp.async.wait_group 0;" ::: "memory");
}

// ---------------- consolidated weight repacks ----------------
__global__ void repack_all_kernel(WPtrs P, unsigned char* __restrict__ wp) {
    const int BIG = 8 * 36 * 16384;
    int idx = blockIdx.x * blockDim.x + threadIdx.x;
    if (idx < BIG) {
        int slot = idx / (36 * 16384);
        int r = idx - slot * (36 * 16384);
        int kc = r & 63;
        int oc = (r >> 6) & 255;
        int sub = r >> 14;
        int tap = sub >> 2, cc2 = sub & 3;
        int ci = (cc2 << 6) + kc;
        float v = P.w[slot][((size_t)oc * 256 + ci) * 9 + tap];
        __nv_bfloat16 hb = __float2bfloat16(v);
        __nv_bfloat16 lb = __float2bfloat16(v - __bfloat162float(hb));
        int half = oc >> 7, ocl = oc & 127;
        uint32_t ofs = (uint32_t)ocl * 128u + (((uint32_t)kc * 2u) ^ (((uint32_t)ocl & 7u) << 4));
        size_t base = (size_t)(slot * 36 + sub) * 65536 + (size_t)(half * 2) * 16384;
        *(unsigned short*)(wp + base + ofs) = *(unsigned short*)&hb;
        *(unsigned short*)(wp + base + 16384 + ofs) = *(unsigned short*)&lb;
    } else {
        int r = idx - BIG;
        if (r >= 9 * 16384) return;
        int kc = r & 63;
        int oc = (r >> 6) & 255;
        int tap = r >> 14;
        int ci = kc;
        float v = (ci < 32) ? P.w[8][((size_t)oc * 32 + ci) * 9 + tap] : 0.f;
        __nv_bfloat16 hb = __float2bfloat16(v);
        __nv_bfloat16 lb = __float2bfloat16(v - __bfloat162float(hb));
        int half = oc >> 7, ocl = oc & 127;
        uint32_t ofs = (uint32_t)ocl * 128u + (((uint32_t)kc * 2u) ^ (((uint32_t)ocl & 7u) << 4));
        size_t base = (size_t)(324 + tap) * 65536 + (size_t)(half * 2) * 16384;
        *(unsigned short*)(wp + base + ofs) = *(unsigned short*)&hb;
        *(unsigned short*)(wp + base + 16384 + ofs) = *(unsigned short*)&lb;
    }
}

// OR-conv: rotated ring source tap, 36 subs at 288*65536
__global__ void repack_or_tc_kernel(const float* __restrict__ w,
                                    unsigned char* __restrict__ wp) {
    int idx = blockIdx.x * blockDim.x + threadIdx.x;
    if (idx >= 36 * 16384) return;
    int kc = idx & 63;
    int oc = (idx >> 6) & 255;
    int sub = idx >> 14;
    int tap = sub >> 2, cc2 = sub & 3;
    int ci = (cc2 << 6) + kc;
    int o = oc >> 3, r = oc & 7;
    int s;
    if (tap == 4) {
        s = 4;
    } else {
        int j = 0;
#pragma unroll
        for (int t = 0; t < 8; t++)
            if (c_ring[t] == tap) j = t;
        s = c_ring[(j - r + 8) & 7];
    }
    float v = w[((size_t)o * CC + ci) * 9 + s];
    __nv_bfloat16 hb = __float2bfloat16(v);
    __nv_bfloat16 lb = __float2bfloat16(v - __bfloat162float(hb));
    int half = oc >> 7, ocl = oc & 127;
    uint32_t ofs = (uint32_t)ocl * 128u + (((uint32_t)kc * 2u) ^ (((uint32_t)ocl & 7u) << 4));
    size_t base = (size_t)(288 + sub) * 65536 + (size_t)(half * 2) * 16384;
    *(unsigned short*)(wp + base + ofs) = *(unsigned short*)&hb;
    *(unsigned short*)(wp + base + 16384 + ofs) = *(unsigned short*)&lb;
}

// head weights layout wt[k*4096 + ci*16 + oc]:
// [0,4096) fam_reg_hw OC5 NK1 | [4096,8192) fam_cls_hw OC15 NK1
// [8192,45056) odm_cls_hw OC15 NK9 | [45056,81920) odm_reg_hw OC5 NK9
__global__ void repack_heads_kernel(const float* __restrict__ w0, const float* __restrict__ w1,
                                    const float* __restrict__ w2, const float* __restrict__ w3,
                                    float* __restrict__ wt) {
    int idx = blockIdx.x * blockDim.x + threadIdx.x;
    if (idx >= 81920) return;
    const float* w;
    int OC, NK, r;
    if (idx < 4096) { w = w0; OC = 5; NK = 1; r = idx; }
    else if (idx < 8192) { w = w1; OC = 15; NK = 1; r = idx - 4096; }
    else if (idx < 45056) { w = w2; OC = 15; NK = 9; r = idx - 8192; }
    else { w = w3; OC = 5; NK = 9; r = idx - 45056; }
    int oc = r & 15;
    int ci = (r >> 4) & 255;
    int k = r >> 12;
    wt[idx] = (oc < OC) ? w[((size_t)oc * 256 + ci) * NK + k] : 0.f;
}

// ---------------- fp32 [C][HW] -> pair-interleaved u32 words ----------------
__global__ void cvt_pair_kernel(const float* __restrict__ x,
                                uint32_t* __restrict__ h, uint32_t* __restrict__ l,
                                int nwords) {
    int i = blockIdx.x * blockDim.x + threadIdx.x;
    if (i >= nwords) return;
    int cp = i >> 14, p = i & 16383;
    float v0 = x[(size_t)(cp * 2) * HW + p];
    float v1 = x[(size_t)(cp * 2 + 1) * HW + p];
    unsigned short h0 = bf16u(v0), h1 = bf16u(v1);
    float l0f = v0 - ubf(h0), l1f = v1 - ubf(h1);
    h[i] = (uint32_t)h0 | ((uint32_t)h1 << 16);
    l[i] = (uint32_t)bf16u(l0f) | ((uint32_t)bf16u(l1f) << 16);
}

// ---------------- shared MMA core pieces ----------------
__device__ __forceinline__ void mma_substage(uint32_t aA, uint32_t aB, int half,
                                             int mrow0, int nbase, int lrow, int lcol16,
                                             float acc[4][8][4]) {
#pragma unroll
    for (int ks = 0; ks < 4; ks++) {
        int kb = ks * 32;
        uint32_t Ah[4][4], Al[4][4];
#pragma unroll
        for (int mt = 0; mt < 4; mt++) {
            int row = mrow0 + mt * 16 + lrow;
            uint32_t roff = (uint32_t)row * 128u +
                            (((uint32_t)(kb + lcol16)) ^ (((uint32_t)row & 7u) << 4));
            ldm4(Ah[mt], aA + (half * 2 + 0) * 16384 + roff);
            ldm4(Al[mt], aA + (half * 2 + 1) * 16384 + roff);
        }
        {
            uint32_t Bh[4][4];
#pragma unroll
            for (int nt = 0; nt < 4; nt++) {
                int row = nbase + nt * 16 + lrow;
                uint32_t roff = (uint32_t)row * 128u +
                                (((uint32_t)(kb + lcol16)) ^ (((uint32_t)row & 7u) << 4));
                ldm4(Bh[nt], aB + roff);
            }
#pragma unroll
            for (int mt = 0; mt < 4; mt++)
#pragma unroll
                for (int nt = 0; nt < 4; nt++) {
                    mma_bf16(acc[mt][nt * 2 + 0], Ah[mt], Bh[nt][0], Bh[nt][2]);
                    mma_bf16(acc[mt][nt * 2 + 0], Al[mt], Bh[nt][0], Bh[nt][2]);
                    mma_bf16(acc[mt][nt * 2 + 1], Ah[mt], Bh[nt][1], Bh[nt][3]);
                    mma_bf16(acc[mt][nt * 2 + 1], Al[mt], Bh[nt][1], Bh[nt][3]);
                }
        }
        {
            uint32_t Bl[4][4];
#pragma unroll
            for (int nt = 0; nt < 4; nt++) {
                int row = nbase + nt * 16 + lrow;
                uint32_t roff = (uint32_t)row * 128u +
                                (((uint32_t)(kb + lcol16)) ^ (((uint32_t)row & 7u) << 4));
                ldm4(Bl[nt], aB + 16384 + roff);
            }
#pragma unroll
            for (int mt = 0; mt < 4; mt++)
#pragma unroll
                for (int nt = 0; nt < 4; nt++) {
                    mma_bf16(acc[mt][nt * 2 + 0], Ah[mt], Bl[nt][0], Bl[nt][2]);
                    mma_bf16(acc[mt][nt * 2 + 1], Ah[mt], Bl[nt][1], Bl[nt][3]);
                }
        }
    }
}

// epilogue: optional fp32 write, shfl-packed bf16-pair write, optional smem tile dump
__device__ __forceinline__ void mma_epilogue(float acc[4][8][4], int mbase, int nbase,
                                             int lane, int y, const float* bias,
                                             int relu, int bias_div, int writeF, int writeP,
                                             float* Yf, unsigned short* Yh,
                                             unsigned short* Yl, float* stile) {
    int qr = lane >> 2, qc = lane & 3;
#pragma unroll
    for (int mt = 0; mt < 4; mt++) {
#pragma unroll
        for (int nf = 0; nf < 8; nf++) {
#pragma unroll
            for (int p = 0; p < 2; p++) {
                int oc = mbase + mt * 16 + qr + p * 8;
                int pxo = nbase + nf * 8 + qc * 2;
                float bv = bias[oc / bias_div];
                float v0 = acc[mt][nf][p * 2 + 0] + bv;
                float v1 = acc[mt][nf][p * 2 + 1] + bv;
                if (relu) { v0 = fmaxf(v0, 0.f); v1 = fmaxf(v1, 0.f); }
                if (stile) {
                    stile[oc * 132 + pxo] = v0;
                    stile[oc * 132 + pxo + 1] = v1;
                }
                if (writeF) {
                    *(float2*)(Yf + (size_t)oc * HW + (size_t)y * Ww + pxo) =
                        make_float2(v0, v1);
                }
                if (writeP) {
                    unsigned short hs0 = bf16u(v0), hs1 = bf16u(v1);
                    unsigned short ls0 = bf16u(v0 - ubf(hs0)), ls1 = bf16u(v1 - ubf(hs1));
                    uint32_t myh = (uint32_t)hs0 | ((uint32_t)hs1 << 16);
                    uint32_t myl = (uint32_t)ls0 | ((uint32_t)ls1 << 16);
                    uint32_t ph = __shfl_down_sync(0xFFFFFFFFu, myh, 4);
                    uint32_t pl = __shfl_down_sync(0xFFFFFFFFu, myl, 4);
                    if (!(qr & 1)) {
                        uint32_t wh0 = (myh & 0xFFFFu) | (ph << 16);
                        uint32_t wh1 = (myh >> 16) | (ph & 0xFFFF0000u);
                        uint32_t wl0 = (myl & 0xFFFFu) | (pl << 16);
                        uint32_t wl1 = (myl >> 16) | (pl & 0xFFFF0000u);
                        size_t w = (size_t)(oc >> 1) * HW + (size_t)y * Ww + pxo;
                        *(uint2*)(Yh + w * 2) = make_uint2(wh0, wh1);
                        *(uint2*)(Yl + w * 2) = make_uint2(wl0, wl1);
                    }
                }
            }
        }
    }
}

__device__ __forceinline__ void load_bregs(const uint32_t* __restrict__ Xrole,
                                           int y, int px, int sub, int ncc, int CI,
                                           uint32_t breg[8][4]) {
    int tap = sub / ncc;
    int ci0 = (sub - tap * ncc) << 6;
    int dy = tap / 3 - 1, dx = tap % 3 - 1;
    int ysrc = y + dy, xsrc = px + dx;
    bool ok = (ysrc >= 0) && (ysrc < Hh) && (xsrc >= 0) && (xsrc < Ww);
    int poff = ysrc * Ww + xsrc;
    int prb = ci0 >> 1;
#pragma unroll
    for (int g = 0; g < 8; g++) {
#pragma unroll
        for (int q = 0; q < 4; q++) {
            int ci = ci0 + (g * 4 + q) * 2;
            breg[g][q] = (ok && ci < CI) ? Xrole[(size_t)(prb + g * 4 + q) * HW + poff] : 0u;
        }
    }
}

// ---------------- HMMA conv: pipelined A + B, optional fused 1x1 head ----------
#define SMEMH 196608
__global__ void __launch_bounds__(256, 1)
conv_hmma_kernel(const unsigned char* __restrict__ wpack,
                 const uint32_t* __restrict__ Xh, const uint32_t* __restrict__ Xl,
                 const float* __restrict__ bias, float* __restrict__ Yf,
                 unsigned short* __restrict__ Yh, unsigned short* __restrict__ Yl,
                 int CI, int relu, int bias_div, int writeF, int writeP,
                 const float* __restrict__ hw, const float* __restrict__ hbias,
                 float* __restrict__ hout, int headOC) {
    extern __shared__ unsigned char sm[];
    uint32_t aSm = smem_u32(sm);

    int tid = threadIdx.x;
    int y = blockIdx.x;
    int lane = tid & 31, wid = tid >> 5;
    int wm = wid >> 1, wn = wid & 1;
    int mbase = wm * 64;
    int half = mbase >> 7;
    int mrow0 = mbase & 127;
    int nbase = wn * 64;
    int lrow = (lane & 7) + ((lane >> 3) & 1) * 8;
    int lcol16 = (lane >> 4) * 16;
    int role = tid >> 7;
    int px = tid & 127;
    int ncc = (CI + 63) >> 6;
    int nsub = 9 * ncc;
    uint32_t bofs[8];
#pragma unroll
    for (int g = 0; g < 8; g++)
        bofs[g] = (uint32_t)px * 128u + (((uint32_t)g << 4) ^ (((uint32_t)px & 7u) << 4)) +
                  role * 16384u;

    float acc[4][8][4];
#pragma unroll
    for (int a = 0; a < 4; a++)
#pragma unroll
        for (int b = 0; b < 8; b++)
#pragma unroll
            for (int c = 0; c < 4; c++) acc[a][b][c] = 0.f;

    const uint32_t* Xrole = role ? Xl : Xh;

    uint32_t breg[8][4];
    load_bregs(Xrole, y, px, 0, ncc, CI, breg);
    cp_async_tile(aSm, wpack, tid);  // A[0]

    for (int sub = 0; sub < nsub; sub++) {
        uint32_t aA = aSm + (uint32_t)(sub & 1) * 65536u;
        uint32_t aB = aSm + 131072u + (uint32_t)(sub & 1) * 32768u;
#pragma unroll
        for (int g = 0; g < 8; g++)
            *(uint4*)(sm + (aB - aSm) + bofs[g]) = make_uint4(breg[g][0], breg[g][1],
                                                              breg[g][2], breg[g][3]);
        cp_async_wait0();
        __syncthreads();
        if (sub + 1 < nsub) {
            cp_async_tile(aSm + (uint32_t)((sub + 1) & 1) * 65536u,
                          wpack + (size_t)(sub + 1) * 65536, tid);
            load_bregs(Xrole, y, px, sub + 1, ncc, CI, breg);
        }
        mma_substage(aA, aB, half, mrow0, nbase, lrow, lcol16, acc);
    }

    float* stile = headOC ? (float*)sm : (float*)0;
    if (headOC) __syncthreads();  // all warps done with smem A/B before tile dump

    mma_epilogue(acc, mbase, nbase, lane, y, bias, relu, bias_div, writeF, writeP,
                 Yf, Yh, Yl, stile);

    if (headOC) {
        __syncthreads();
        if (tid < 128) {
            float s[16];
#pragma unroll
            for (int h = 0; h < 16; h++) s[h] = 0.f;
            for (int h = 0; h < headOC; h++) s[h] = hbias[h];
            for (int oc = 0; oc < 256; oc++) {
                float v = stile[oc * 132 + tid];
#pragma unroll
                for (int h = 0; h < 15; h++)
                    if (h < headOC) s[h] += hw[oc * 16 + h] * v;
            }
            for (int h = 0; h < headOC; h++)
                hout[(size_t)h * HW + (size_t)y * Ww + tid] = s[h];
        }
    }
}

// ---------------- deformable HMMA conv (bilinear gather B), pipelined ----------
#define SMEMD 224256
__global__ void __launch_bounds__(256, 1)
conv_deform_kernel(const unsigned char* __restrict__ wpack,
                   const float* __restrict__ feats, const float* __restrict__ refine,
                   const float* __restrict__ bias,
                   unsigned short* __restrict__ Yh, unsigned short* __restrict__ Yl) {
    extern __shared__ unsigned char sm[];
    uint32_t aSm = smem_u32(sm);
    unsigned short* s_idx = (unsigned short*)(sm + 196608);
    float* s_wt = (float*)(sm + 196608 + 9216);

    int tid = threadIdx.x;
    int y = blockIdx.x;
    int lane = tid & 31, wid = tid >> 5;
    int wm = wid >> 1, wn = wid & 1;
    int mbase = wm * 64;
    int half = mbase >> 7;
    int mrow0 = mbase & 127;
    int nbase = wn * 64;
    int lrow = (lane & 7) + ((lane >> 3) & 1) * 8;
    int lcol16 = (lane >> 4) * 16;
    int role = tid >> 7;
    int px = tid & 127;

    for (int e = tid; e < 128 * 9; e += 256) {
        int pxe = e / 9, k = e % 9;
        int p = y * Ww + pxe;
        float axc = refine[p * 5 + 0] * 0.125f;
        float ayc = refine[p * 5 + 1] * 0.125f;
        float aw = refine[p * 5 + 2] * 0.125f;
        float ah = refine[p * 5 + 3] * 0.125f;
        float aa = refine[p * 5 + 4];
        float cs = cosf(aa), sn = sinf(aa);
        float kx = (float)(k % 3 - 1);
        float ky = (float)(k / 3 - 1);
        float ddx = (aw * (1.f / 3.f)) * kx;
        float ddy = (ah * (1.f / 3.f)) * ky;
        float xs = cs * ddx - sn * ddy + axc;
        float ys = sn * ddx + cs * ddy + ayc;
        float x0f = floorf(xs), y0f = floorf(ys);
        float wx1 = xs - x0f, wx0 = 1.f - wx1;
        float wy1 = ys - y0f, wy0 = 1.f - wy1;
        int x0 = (int)x0f, y0 = (int)y0f;
#pragma unroll
        for (int c = 0; c < 4; c++) {
            int xi = x0 + (c & 1);
            int yi = y0 + (c >> 1);
            float ww = ((c & 1) ? wx1 : wx0) * ((c >> 1) ? wy1 : wy0);
            bool valid = (xi >= 0 && xi < Ww && yi >= 0 && yi < Hh);
            int xc = min(max(xi, 0), Ww - 1);
            int yc = min(max(yi, 0), Hh - 1);
            s_idx[(k * 4 + c) * 128 + pxe] = (unsigned short)(yc * Ww + xc);
            s_wt[(k * 4 + c) * 128 + pxe] = valid ? ww : 0.f;
        }
    }

    float acc[4][8][4];
#pragma unroll
    for (int a = 0; a < 4; a++)
#pragma unroll
        for (int b = 0; b < 8; b++)
#pragma unroll
            for (int c = 0; c < 4; c++) acc[a][b][c] = 0.f;

    cp_async_tile(aSm, wpack, tid);
    __syncthreads();

    uint32_t hv[16], lv[16];
    {
        int tap = 0, ci0 = 0;
        int I0 = s_idx[(tap * 4 + 0) * 128 + px];
        int I1 = s_idx[(tap * 4 + 1) * 128 + px];
        int I2 = s_idx[(tap * 4 + 2) * 128 + px];
        int I3 = s_idx[(tap * 4 + 3) * 128 + px];
        float W0 = s_wt[(tap * 4 + 0) * 128 + px];
        float W1 = s_wt[(tap * 4 + 1) * 128 + px];
        float W2 = s_wt[(tap * 4 + 2) * 128 + px];
        float W3 = s_wt[(tap * 4 + 3) * 128 + px];
        int cbase = ci0 + role * 32;
#pragma unroll
        for (int j = 0; j < 16; j++) {
            const float* f0 = feats + (size_t)(cbase + j * 2) * HW;
            const float* f1 = feats + (size_t)(cbase + j * 2 + 1) * HW;
            float v0 = f0[I0] * W0 + f0[I1] * W1 + f0[I2] * W2 + f0[I3] * W3;
            float v1 = f1[I0] * W0 + f1[I1] * W1 + f1[I2] * W2 + f1[I3] * W3;
            unsigned short h0 = bf16u(v0), h1 = bf16u(v1);
            hv[j] = (uint32_t)h0 | ((uint32_t)h1 << 16);
            lv[j] = (uint32_t)bf16u(v0 - ubf(h0)) | ((uint32_t)bf16u(v1 - ubf(h1)) << 16);
        }
    }

    for (int sub = 0; sub < 36; sub++) {
        uint32_t aA = aSm + (uint32_t)(sub & 1) * 65536u;
        uint32_t aB = aSm + 131072u + (uint32_t)(sub & 1) * 32768u;
#pragma unroll
        for (int gg = 0; gg < 4; gg++) {
            uint32_t ofs = (uint32_t)px * 128u +
                           (((uint32_t)(role * 4 + gg) << 4) ^ (((uint32_t)px & 7u) << 4));
            *(uint4*)(sm + (aB - aSm) + ofs) = *(uint4*)&hv[gg * 4];
            *(uint4*)(sm + (aB - aSm) + 16384 + ofs) = *(uint4*)&lv[gg * 4];
        }
        cp_async_wait0();
        __syncthreads();
        if (sub + 1 < 36) {
            cp_async_tile(aSm + (uint32_t)((sub + 1) & 1) * 65536u,
                          wpack + (size_t)(sub + 1) * 65536, tid);
            int tap = (sub + 1) >> 2;
            int ci0 = ((sub + 1) & 3) << 6;
            int I0 = s_idx[(tap * 4 + 0) * 128 + px];
            int I1 = s_idx[(tap * 4 + 1) * 128 + px];
            int I2 = s_idx[(tap * 4 + 2) * 128 + px];
            int I3 = s_idx[(tap * 4 + 3) * 128 + px];
            float W0 = s_wt[(tap * 4 + 0) * 128 + px];
            float W1 = s_wt[(tap * 4 + 1) * 128 + px];
            float W2 = s_wt[(tap * 4 + 2) * 128 + px];
            float W3 = s_wt[(tap * 4 + 3) * 128 + px];
            int cbase = ci0 + role * 32;
#pragma unroll
            for (int j = 0; j < 16; j++) {
                const float* f0 = feats + (size_t)(cbase + j * 2) * HW;
                const float* f1 = feats + (size_t)(cbase + j * 2 + 1) * HW;
                float v0 = f0[I0] * W0 + f0[I1] * W1 + f0[I2] * W2 + f0[I3] * W3;
                float v1 = f1[I0] * W0 + f1[I1] * W1 + f1[I2] * W2 + f1[I3] * W3;
                unsigned short h0 = bf16u(v0), h1 = bf16u(v1);
                hv[j] = (uint32_t)h0 | ((uint32_t)h1 << 16);
                lv[j] = (uint32_t)bf16u(v0 - ubf(h0)) | ((uint32_t)bf16u(v1 - ubf(h1)) << 16);
            }
        }
        mma_substage(aA, aB, half, mrow0, nbase, lrow, lcol16, acc);
    }

    mma_epilogue(acc, mbase, nbase, lane, y, bias, 1, 1, 0, 1, (float*)0, Yh, Yl, (float*)0);
}

// ---------------- head partial conv (one 3x3 tap per block, ODM heads) ----------
__global__ void __launch_bounds__(128, 4)
head_part_kernel(const float* __restrict__ wt, const float* __restrict__ X,
                 float* __restrict__ part, int CI, int NK) {
    __shared__ float Ws[8][16];
    __shared__ float Xs[8][128];

    int y = blockIdx.x;
    int k = blockIdx.y;
    int tid = threadIdx.x;
    int tx = tid & 31;
    int ty = tid >> 5;

    float acc[4][4];
#pragma unroll
    for (int i = 0; i < 4; i++)
#pragma unroll
        for (int j = 0; j < 4; j++) acc[i][j] = 0.f;

    int dy = (NK == 9) ? (k / 3 - 1) : 0;
    int dx = (NK == 9) ? (k % 3 - 1) : 0;
    int yy = y + dy;
    bool rowok = (yy >= 0 && yy < Hh);

    for (int ci0 = 0; ci0 < CI; ci0 += 8) {
        {
            int kk = tid >> 4;
            int m = tid & 15;
            Ws[kk][m] = wt[((size_t)(k * CI + ci0 + kk)) * 16 + m];
        }
        {
            int kk = tid >> 4;
            int lanex = tid & 15;
            const float* xrow = X + (size_t)(ci0 + kk) * HW + yy * Ww;
#pragma unroll
            for (int j = 0; j < 8; j++) {
                int n = lanex + 16 * j;
                int xx = n + dx;
                float v = 0.f;
                if (rowok && xx >= 0 && xx < Ww) v = xrow[xx];
                Xs[kk][n] = v;
            }
        }
        __syncthreads();
#pragma unroll
        for (int kk = 0; kk < 8; kk++) {
            float a[4], b[4];
            *(float4*)a = *(const float4*)&Ws[kk][ty * 4];
            *(float4*)b = *(const float4*)&Xs[kk][tx * 4];
#pragma unroll
            for (int i = 0; i < 4; i++)
#pragma unroll
                for (int j = 0; j < 4; j++) acc[i][j] += a[i] * b[j];
        }
        __syncthreads();
    }

#pragma unroll
    for (int i = 0; i < 4; i++) {
        int m = ty * 4 + i;
#pragma unroll
        for (int j = 0; j < 4; j++) {
            int n = tx * 4 + j;
            part[((size_t)k * 16 + m) * HW + (size_t)y * Ww + n] = acc[i][j];
        }
    }
}

__global__ void head_reduce_kernel(const float* __restrict__ part,
                                   const float* __restrict__ bias,
                                   float* __restrict__ Y, int OC, int NK) {
    int idx = blockIdx.x * blockDim.x + threadIdx.x;
    if (idx >= OC * HW) return;
    int m = idx / HW, p = idx - m * HW;
    float s = bias[m];
    for (int t = 0; t < NK; t++) s += part[((size_t)t * 16 + m) * HW + p];
    Y[(size_t)m * HW + p] = s;
}

// ---------------- anchors + rbox decode ----------------
__global__ void decode_kernel(const float* __restrict__ bbox,
                              float* __restrict__ anchors_out,
                              float* __restrict__ refine_out) {
    int p = blockIdx.x * blockDim.x + threadIdx.x;
    if (p >= HW) return;
    int x = p & 127, yv = p >> 7;
    float ax = x * 8.f + 3.5f;
    float ay = yv * 8.f + 3.5f;
    anchors_out[p * 5 + 0] = ax;
    anchors_out[p * 5 + 1] = ay;
    anchors_out[p * 5 + 2] = 32.f;
    anchors_out[p * 5 + 3] = 32.f;
    anchors_out[p * 5 + 4] = 0.f;

    float dx = bbox[p];
    float dyv = bbox[HW + p];
    float dw = bbox[2 * HW + p];
    float dh = bbox[3 * HW + p];
    float dt = bbox[4 * HW + p];
    const float MR = 13.815510557964274f;
    dw = fminf(fmaxf(dw, -MR), MR);
    dh = fminf(fmaxf(dh, -MR), MR);
    float gx = dx * 32.f + ax;
    float gy = dyv * 32.f + ay;
    float gw = 32.f * expf(dw);
    float gh = 32.f * expf(dh);
    const float PI = 3.14159265358979323846f;
    float r = fmodf(dt + PI * 0.25f, PI);
    if (r < 0.f) r += PI;
    float ga = r - PI * 0.25f;
    refine_out[p * 5 + 0] = gx;
    refine_out[p * 5 + 1] = gy;
    refine_out[p * 5 + 2] = gw;
    refine_out[p * 5 + 3] = gh;
    refine_out[p * 5 + 4] = ga;
}

// ---------------- rotation-invariant max pooling on pair tensors ----------------
__global__ void maxpool8_kernel(const uint32_t* __restrict__ oh,
                                const uint32_t* __restrict__ ol,
                                unsigned short* __restrict__ ph,
                                unsigned short* __restrict__ pl) {
    int p = blockIdx.x * blockDim.x + threadIdx.x;
    int i = blockIdx.y;
    if (p >= HW) return;
    float m = -1e30f;
#pragma unroll
    for (int r2 = 0; r2 < 4; r2++) {
        size_t w = (size_t)(i * 4 + r2) * HW + p;
        uint32_t wh = oh[w], wl = ol[w];
        float v0 = half_of(wh, 0) + half_of(wl, 0);
        float v1 = half_of(wh, 1) + half_of(wl, 1);
        m = fmaxf(m, fmaxf(v0, v1));
    }
    size_t wo = ((size_t)(i >> 1) * HW + p) * 2 + (i & 1);
    unsigned short hb = bf16u(m);
    ph[wo] = hb;
    pl[wo] = bf16u(m - ubf(hb));
}

// ---------------- host orchestration ----------------
extern "C" void kernel_launch(void* const* d_in, const int* in_sizes, int n_in,
                              void* d_out, int out_size) {
    (void)in_sizes; (void)n_in; (void)out_size;

    const float* feats = (const float*)d_in[0];
    const float* fam_reg_w0 = (const float*)d_in[1];
    const float* fam_reg_b0 = (const float*)d_in[2];
    const float* fam_reg_w1 = (const float*)d_in[3];
    const float* fam_reg_b1 = (const float*)d_in[4];
    const float* fam_reg_hw = (const float*)d_in[5];
    const float* fam_reg_hb = (const float*)d_in[6];
    const float* fam_cls_w0 = (const float*)d_in[7];
    const float* fam_cls_b0 = (const float*)d_in[8];
    const float* fam_cls_w1 = (const float*)d_in[9];
    const float* fam_cls_b1 = (const float*)d_in[10];
    const float* fam_cls_hw = (const float*)d_in[11];
    const float* fam_cls_hb = (const float*)d_in[12];
    const float* align_w = (const float*)d_in[13];
    const float* align_b = (const float*)d_in[14];
    const float* or_w = (const float*)d_in[15];
    const float* or_b = (const float*)d_in[16];
    const float* odm_reg_w0 = (const float*)d_in[17];
    const float* odm_reg_b0 = (const float*)d_in[18];
    const float* odm_reg_w1 = (const float*)d_in[19];
    const float* odm_reg_b1 = (const float*)d_in[20];
    const float* odm_reg_hw = (const float*)d_in[21];
    const float* odm_reg_hb = (const float*)d_in[22];
    const float* odm_cls_w0 = (const float*)d_in[23];
    const float* odm_cls_b0 = (const float*)d_in[24];
    const float* odm_cls_w1 = (const float*)d_in[25];
    const float* odm_cls_b1 = (const float*)d_in[26];
    const float* odm_cls_hw = (const float*)d_in[27];
    const float* odm_cls_hb = (const float*)d_in[28];

    float* out = (float*)d_out;
    float* o_famcls = out;
    float* o_fambbox = out + 245760;
    float* o_odmcls = out + 327680;
    float* o_odmbbox = out + 573440;
    float* o_anchors = out + 655360;
    float* o_refine = out + 737280;

    float *b1, *b2, *wts, *hd, *hd2;
    unsigned char* wp;
    uint32_t *p0h, *p0l, *p1h, *p1l, *p2h, *p2l, *p3h, *p3l, *pdh, *pdl;
    cudaGetSymbolAddress((void**)&b1, g_b1);
    cudaGetSymbolAddress((void**)&b2, g_b2);
    cudaGetSymbolAddress((void**)&hd, g_head);
    cudaGetSymbolAddress((void**)&hd2, g_head2);
    cudaGetSymbolAddress((void**)&wts, g_wt_small);
    cudaGetSymbolAddress((void**)&wp, g_wpack);
    cudaGetSymbolAddress((void**)&p0h, g_p0h);
    cudaGetSymbolAddress((void**)&p0l, g_p0l);
    cudaGetSymbolAddress((void**)&p1h, g_p1h);
    cudaGetSymbolAddress((void**)&p1l, g_p1l);
    cudaGetSymbolAddress((void**)&p2h, g_p2h);
    cudaGetSymbolAddress((void**)&p2l, g_p2l);
    cudaGetSymbolAddress((void**)&p3h, g_p3h);
    cudaGetSymbolAddress((void**)&p3l, g_p3l);
    cudaGetSymbolAddress((void**)&pdh, g_pdh);
    cudaGetSymbolAddress((void**)&pdl, g_pdl);

    cudaFuncSetAttribute(conv_hmma_kernel, cudaFuncAttributeMaxDynamicSharedMemorySize, SMEMH);
    cudaFuncSetAttribute(conv_deform_kernel, cudaFuncAttributeMaxDynamicSharedMemorySize, SMEMD);

    cudaStream_t s1;
    cudaEvent_t ev0, ev1, ev2, ev3;
    cudaStreamCreateWithFlags(&s1, cudaStreamNonBlocking);
    cudaEventCreateWithFlags(&ev0, cudaEventDisableTiming);
    cudaEventCreateWithFlags(&ev1, cudaEventDisableTiming);
    cudaEventCreateWithFlags(&ev2, cudaEventDisableTiming);
    cudaEventCreateWithFlags(&ev3, cudaEventDisableTiming);

    const size_t SLOT = 36 * 65536;

    // ---- prologue (stream 0) ----
    cvt_pair_kernel<<<8192, 256>>>(feats, p0h, p0l, 128 * HW);
    repack_heads_kernel<<<320, 256>>>(fam_reg_hw, fam_cls_hw, odm_cls_hw, odm_reg_hw, wts);
    {
        WPtrs P;
        P.w[0] = fam_reg_w0; P.w[1] = fam_reg_w1; P.w[2] = fam_cls_w0; P.w[3] = fam_cls_w1;
        P.w[4] = align_w; P.w[5] = odm_cls_w1; P.w[6] = odm_reg_w0; P.w[7] = odm_reg_w1;
        P.w[8] = odm_cls_w0;
        repack_all_kernel<<<(8 * 36 * 16384 + 9 * 16384 + 255) / 256, 256>>>(P, wp);
    }
    repack_or_tc_kernel<<<2304, 256>>>(or_w, wp);

    // ---- fork 1: FAM reg + decode + deform (s0) || FAM cls (s1) ----
    cudaEventRecord(ev0, 0);
    cudaStreamWaitEvent(s1, ev0, 0);

    // s0: FAM reg chain: p0 -> p1 pair -> fused head -> decode -> deform -> p1
    conv_hmma_kernel<<<128, 256, SMEMH>>>(wp + 0 * SLOT, p0h, p0l, fam_reg_b0, (float*)0,
                                          (unsigned short*)p1h, (unsigned short*)p1l,
                                          256, 1, 1, 0, 1, (float*)0, (float*)0, (float*)0, 0);
    conv_hmma_kernel<<<128, 256, SMEMH>>>(wp + 1 * SLOT, p1h, p1l, fam_reg_b1, (float*)0,
                                          (unsigned short*)0, (unsigned short*)0,
                                          256, 1, 1, 0, 0, wts + 0, fam_reg_hb, o_fambbox, 5);
    decode_kernel<<<HW / 256, 256>>>(o_fambbox, o_anchors, o_refine);
    conv_deform_kernel<<<128, 256, SMEMD>>>(wp + 4 * SLOT, feats, o_refine, align_b,
                                            (unsigned short*)p1h, (unsigned short*)p1l);

    // s1: FAM cls chain: p0 -> p2 pair -> fused head
    conv_hmma_kernel<<<128, 256, SMEMH, s1>>>(wp + 2 * SLOT, p0h, p0l, fam_cls_b0, (float*)0,
                                              (unsigned short*)p2h, (unsigned short*)p2l,
                                              256, 1, 1, 0, 1, (float*)0, (float*)0, (float*)0, 0);
    conv_hmma_kernel<<<128, 256, SMEMH, s1>>>(wp + 3 * SLOT, p2h, p2l, fam_cls_b1, (float*)0,
                                              (unsigned short*)0, (unsigned short*)0,
                                              256, 1, 1, 0, 0, wts + 4096, fam_cls_hb, o_famcls, 15);

    // join 1 (OR writes p2, which FAM cls reads)
    cudaEventRecord(ev1, s1);
    cudaStreamWaitEvent(0, ev1, 0);

    // ---- middle (s0): OR conv -> p2, pool -> pd ----
    conv_hmma_kernel<<<128, 256, SMEMH>>>(wp + 8 * SLOT, p1h, p1l, or_b, (float*)0,
                                          (unsigned short*)p2h, (unsigned short*)p2l,
                                          256, 0, 8, 0, 1, (float*)0, (float*)0, (float*)0, 0);
    {
        dim3 g(HW / 256, 32);
        maxpool8_kernel<<<g, 256>>>(p2h, p2l, (unsigned short*)pdh, (unsigned short*)pdl);
    }

    // ---- fork 2: ODM cls (s0) || ODM reg (s1) ----
    cudaEventRecord(ev2, 0);
    cudaStreamWaitEvent(s1, ev2, 0);

    // s0: ODM cls: pd -> p3 pair, p3 -> b1 fp32, 3x3 head
    conv_hmma_kernel<<<128, 256, SMEMH>>>(wp + 9 * SLOT, pdh, pdl, odm_cls_b0, (float*)0,
                                          (unsigned short*)p3h, (unsigned short*)p3l,
                                          32, 1, 1, 0, 1, (float*)0, (float*)0, (float*)0, 0);
    conv_hmma_kernel<<<128, 256, SMEMH>>>(wp + 5 * SLOT, p3h, p3l, odm_cls_b1, b1,
                                          (unsigned short*)0, (unsigned short*)0,
                                          256, 1, 1, 1, 0, (float*)0, (float*)0, (float*)0, 0);
    head_part_kernel<<<dim3(128, 9), 128>>>(wts + 8192, b1, hd, 256, 9);
    head_reduce_kernel<<<(15 * HW + 255) / 256, 256>>>(hd, odm_cls_hb, o_odmcls, 15, 9);

    // s1: ODM reg: p2 -> p0 pair, p0 -> b2 fp32, 3x3 head
    conv_hmma_kernel<<<128, 256, SMEMH, s1>>>(wp + 6 * SLOT, p2h, p2l, odm_reg_b0, (float*)0,
                                              (unsigned short*)p0h, (unsigned short*)p0l,
                                              256, 1, 1, 0, 1, (float*)0, (float*)0, (float*)0, 0);
    conv_hmma_kernel<<<128, 256, SMEMH, s1>>>(wp + 7 * SLOT, p0h, p0l, odm_reg_b1, b2,
                                              (unsigned short*)0, (unsigned short*)0,
                                              256, 1, 1, 1, 0, (float*)0, (float*)0, (float*)0, 0);
    head_part_kernel<<<dim3(128, 9), 128, 0, s1>>>(wts + 45056, b2, hd2, 256, 9);
    head_reduce_kernel<<<(5 * HW + 255) / 256, 256, 0, s1>>>(hd2, odm_reg_hb, o_odmbbox, 5, 9);

    // join 2
    cudaEventRecord(ev3, s1);
    cudaStreamWaitEvent(0, ev3, 0);
}

// round 12
// speedup vs baseline: 1.0414x; 1.0414x over previous
#include <cuda_runtime.h>
#include <cuda_bf16.h>
#include <math.h>
#include <stdint.h>

#define Hh 128
#define Ww 128
#define HW 16384
#define CC 256

// ---------------- scratch (static __device__, no allocs) ----------------
__device__ float g_b1[CC * HW];
__device__ float g_b2[CC * HW];
__device__ float g_head[9 * 16 * HW];
__device__ float g_head2[9 * 16 * HW];
__device__ float g_wt_small[81920];
__device__ unsigned char g_wpack[333 * 65536];
// pair tensors: u32 word = (bf16 ch 2m) | (bf16 ch 2m+1 << 16), index m*HW + p
__device__ uint32_t g_p0h[128 * HW];
__device__ uint32_t g_p0l[128 * HW];
__device__ uint32_t g_p1h[128 * HW];
__device__ uint32_t g_p1l[128 * HW];
__device__ uint32_t g_p2h[128 * HW];
__device__ uint32_t g_p2l[128 * HW];
__device__ uint32_t g_p3h[128 * HW];
__device__ uint32_t g_p3l[128 * HW];
__device__ uint32_t g_pdh[16 * HW];
__device__ uint32_t g_pdl[16 * HW];

__constant__ int c_ring[8] = {0, 1, 2, 5, 8, 7, 6, 3};

struct WPtrs {
    const float* w[9];
};

// ---------------- helpers ----------------
__device__ __forceinline__ uint32_t smem_u32(const void* p) {
    uint32_t a;
    asm("{ .reg .u64 t; cvta.to.shared.u64 t, %1; cvt.u32.u64 %0, t; }" : "=r"(a) : "l"(p));
    return a;
}
__device__ __forceinline__ void ldm4(uint32_t* r, uint32_t addr) {
    asm volatile("ldmatrix.sync.aligned.m8n8.x4.shared.b16 {%0,%1,%2,%3}, [%4];"
                 : "=r"(r[0]), "=r"(r[1]), "=r"(r[2]), "=r"(r[3]) : "r"(addr));
}
__device__ __forceinline__ void mma_bf16(float* c, const uint32_t* a, uint32_t b0, uint32_t b1) {
    asm volatile(
        "mma.sync.aligned.m16n8k16.row.col.f32.bf16.bf16.f32 "
        "{%0,%1,%2,%3}, {%4,%5,%6,%7}, {%8,%9}, {%0,%1,%2,%3};"
        : "+f"(c[0]), "+f"(c[1]), "+f"(c[2]), "+f"(c[3])
        : "r"(a[0]), "r"(a[1]), "r"(a[2]), "r"(a[3]), "r"(b0), "r"(b1));
}
__device__ __forceinline__ unsigned short bf16u(float v) {
    __nv_bfloat16 b = __float2bfloat16(v);
    return *(unsigned short*)&b;
}
__device__ __forceinline__ float ubf(unsigned short u) {
    __nv_bfloat16 b = *(__nv_bfloat16*)&u;
    return __bfloat162float(b);
}
__device__ __forceinline__ float half_of(uint32_t w, int hi) {
    return ubf((unsigned short)(hi ? (w >> 16) : (w & 0xFFFF)));
}
__device__ __forceinline__ void cp_async_tile(uint32_t dst, const unsigned char* src, int tid) {
#pragma unroll
    for (int i = 0; i < 16; i++) {
        asm volatile("cp.async.cg.shared.global [%0], [%1], 16;"
                     :: "r"(dst + (uint32_t)(tid + i * 256) * 16),
                        "l"(src + (size_t)(tid + i * 256) * 16) : "memory");
    }
    asm volatile("cp.async.commit_group;" ::: "memory");
}
__device__ __forceinline__ void cp_async_wait0() {
    asm volatile("cp.async.wait_group 0;" ::: "memory");
}

// ---------------- consolidated weight repacks ----------------
__global__ void repack_all_kernel(WPtrs P, unsigned char* __restrict__ wp) {
    const int BIG = 8 * 36 * 16384;
    int idx = blockIdx.x * blockDim.x + threadIdx.x;
    if (idx < BIG) {
        int slot = idx / (36 * 16384);
        int r = idx - slot * (36 * 16384);
        int kc = r & 63;
        int oc = (r >> 6) & 255;
        int sub = r >> 14;
        int tap = sub >> 2, cc2 = sub & 3;
        int ci = (cc2 << 6) + kc;
        float v = P.w[slot][((size_t)oc * 256 + ci) * 9 + tap];
        __nv_bfloat16 hb = __float2bfloat16(v);
        __nv_bfloat16 lb = __float2bfloat16(v - __bfloat162float(hb));
        int half = oc >> 7, ocl = oc & 127;
        uint32_t ofs = (uint32_t)ocl * 128u + (((uint32_t)kc * 2u) ^ (((uint32_t)ocl & 7u) << 4));
        size_t base = (size_t)(slot * 36 + sub) * 65536 + (size_t)(half * 2) * 16384;
        *(unsigned short*)(wp + base + ofs) = *(unsigned short*)&hb;
        *(unsigned short*)(wp + base + 16384 + ofs) = *(unsigned short*)&lb;
    } else {
        int r = idx - BIG;
        if (r >= 9 * 16384) return;
        int kc = r & 63;
        int oc = (r >> 6) & 255;
        int tap = r >> 14;
        int ci = kc;
        float v = (ci < 32) ? P.w[8][((size_t)oc * 32 + ci) * 9 + tap] : 0.f;
        __nv_bfloat16 hb = __float2bfloat16(v);
        __nv_bfloat16 lb = __float2bfloat16(v - __bfloat162float(hb));
        int half = oc >> 7, ocl = oc & 127;
        uint32_t ofs = (uint32_t)ocl * 128u + (((uint32_t)kc * 2u) ^ (((uint32_t)ocl & 7u) << 4));
        size_t base = (size_t)(324 + tap) * 65536 + (size_t)(half * 2) * 16384;
        *(unsigned short*)(wp + base + ofs) = *(unsigned short*)&hb;
        *(unsigned short*)(wp + base + 16384 + ofs) = *(unsigned short*)&lb;
    }
}

// OR-conv: rotated ring source tap, 36 subs at 288*65536
__global__ void repack_or_tc_kernel(const float* __restrict__ w,
                                    unsigned char* __restrict__ wp) {
    int idx = blockIdx.x * blockDim.x + threadIdx.x;
    if (idx >= 36 * 16384) return;
    int kc = idx & 63;
    int oc = (idx >> 6) & 255;
    int sub = idx >> 14;
    int tap = sub >> 2, cc2 = sub & 3;
    int ci = (cc2 << 6) + kc;
    int o = oc >> 3, r = oc & 7;
    int s;
    if (tap == 4) {
        s = 4;
    } else {
        int j = 0;
#pragma unroll
        for (int t = 0; t < 8; t++)
            if (c_ring[t] == tap) j = t;
        s = c_ring[(j - r + 8) & 7];
    }
    float v = w[((size_t)o * CC + ci) * 9 + s];
    __nv_bfloat16 hb = __float2bfloat16(v);
    __nv_bfloat16 lb = __float2bfloat16(v - __bfloat162float(hb));
    int half = oc >> 7, ocl = oc & 127;
    uint32_t ofs = (uint32_t)ocl * 128u + (((uint32_t)kc * 2u) ^ (((uint32_t)ocl & 7u) << 4));
    size_t base = (size_t)(288 + sub) * 65536 + (size_t)(half * 2) * 16384;
    *(unsigned short*)(wp + base + ofs) = *(unsigned short*)&hb;
    *(unsigned short*)(wp + base + 16384 + ofs) = *(unsigned short*)&lb;
}

// head weights layout wt[k*4096 + ci*16 + oc]:
// [0,4096) fam_reg_hw OC5 NK1 | [4096,8192) fam_cls_hw OC15 NK1
// [8192,45056) odm_cls_hw OC15 NK9 | [45056,81920) odm_reg_hw OC5 NK9
__global__ void repack_heads_kernel(const float* __restrict__ w0, const float* __restrict__ w1,
                                    const float* __restrict__ w2, const float* __restrict__ w3,
                                    float* __restrict__ wt) {
    int idx = blockIdx.x * blockDim.x + threadIdx.x;
    if (idx >= 81920) return;
    const float* w;
    int OC, NK, r;
    if (idx < 4096) { w = w0; OC = 5; NK = 1; r = idx; }
    else if (idx < 8192) { w = w1; OC = 15; NK = 1; r = idx - 4096; }
    else if (idx < 45056) { w = w2; OC = 15; NK = 9; r = idx - 8192; }
    else { w = w3; OC = 5; NK = 9; r = idx - 45056; }
    int oc = r & 15;
    int ci = (r >> 4) & 255;
    int k = r >> 12;
    wt[idx] = (oc < OC) ? w[((size_t)oc * 256 + ci) * NK + k] : 0.f;
}

// ---------------- fp32 [C][HW] -> pair-interleaved u32 words ----------------
__global__ void cvt_pair_kernel(const float* __restrict__ x,
                                uint32_t* __restrict__ h, uint32_t* __restrict__ l,
                                int nwords) {
    int i = blockIdx.x * blockDim.x + threadIdx.x;
    if (i >= nwords) return;
    int cp = i >> 14, p = i & 16383;
    float v0 = x[(size_t)(cp * 2) * HW + p];
    float v1 = x[(size_t)(cp * 2 + 1) * HW + p];
    unsigned short h0 = bf16u(v0), h1 = bf16u(v1);
    float l0f = v0 - ubf(h0), l1f = v1 - ubf(h1);
    h[i] = (uint32_t)h0 | ((uint32_t)h1 << 16);
    l[i] = (uint32_t)bf16u(l0f) | ((uint32_t)bf16u(l1f) << 16);
}

// ---------------- shared MMA core pieces ----------------
__device__ __forceinline__ void mma_substage(uint32_t aA, uint32_t aB, int half,
                                             int mrow0, int nbase, int lrow, int lcol16,
                                             float acc[4][8][4]) {
#pragma unroll
    for (int ks = 0; ks < 4; ks++) {
        int kb = ks * 32;
        uint32_t Ah[4][4], Al[4][4];
#pragma unroll
        for (int mt = 0; mt < 4; mt++) {
            int row = mrow0 + mt * 16 + lrow;
            uint32_t roff = (uint32_t)row * 128u +
                            (((uint32_t)(kb + lcol16)) ^ (((uint32_t)row & 7u) << 4));
            ldm4(Ah[mt], aA + (half * 2 + 0) * 16384 + roff);
            ldm4(Al[mt], aA + (half * 2 + 1) * 16384 + roff);
        }
        {
            uint32_t Bh[4][4];
#pragma unroll
            for (int nt = 0; nt < 4; nt++) {
                int row = nbase + nt * 16 + lrow;
                uint32_t roff = (uint32_t)row * 128u +
                                (((uint32_t)(kb + lcol16)) ^ (((uint32_t)row & 7u) << 4));
                ldm4(Bh[nt], aB + roff);
            }
#pragma unroll
            for (int mt = 0; mt < 4; mt++)
#pragma unroll
                for (int nt = 0; nt < 4; nt++) {
                    mma_bf16(acc[mt][nt * 2 + 0], Ah[mt], Bh[nt][0], Bh[nt][2]);
                    mma_bf16(acc[mt][nt * 2 + 0], Al[mt], Bh[nt][0], Bh[nt][2]);
                    mma_bf16(acc[mt][nt * 2 + 1], Ah[mt], Bh[nt][1], Bh[nt][3]);
                    mma_bf16(acc[mt][nt * 2 + 1], Al[mt], Bh[nt][1], Bh[nt][3]);
                }
        }
        {
            uint32_t Bl[4][4];
#pragma unroll
            for (int nt = 0; nt < 4; nt++) {
                int row = nbase + nt * 16 + lrow;
                uint32_t roff = (uint32_t)row * 128u +
                                (((uint32_t)(kb + lcol16)) ^ (((uint32_t)row & 7u) << 4));
                ldm4(Bl[nt], aB + 16384 + roff);
            }
#pragma unroll
            for (int mt = 0; mt < 4; mt++)
#pragma unroll
                for (int nt = 0; nt < 4; nt++) {
                    mma_bf16(acc[mt][nt * 2 + 0], Ah[mt], Bl[nt][0], Bl[nt][2]);
                    mma_bf16(acc[mt][nt * 2 + 1], Ah[mt], Bl[nt][1], Bl[nt][3]);
                }
        }
    }
}

// epilogue: optional fp32 write, shfl-packed bf16-pair write, optional smem tile dump
__device__ __forceinline__ void mma_epilogue(float acc[4][8][4], int mbase, int nbase,
                                             int lane, int y, const float* bias,
                                             int relu, int bias_div, int writeF, int writeP,
                                             float* Yf, unsigned short* Yh,
                                             unsigned short* Yl, float* stile) {
    int qr = lane >> 2, qc = lane & 3;
#pragma unroll
    for (int mt = 0; mt < 4; mt++) {
#pragma unroll
        for (int nf = 0; nf < 8; nf++) {
#pragma unroll
            for (int p = 0; p < 2; p++) {
                int oc = mbase + mt * 16 + qr + p * 8;
                int pxo = nbase + nf * 8 + qc * 2;
                float bv = bias[oc / bias_div];
                float v0 = acc[mt][nf][p * 2 + 0] + bv;
                float v1 = acc[mt][nf][p * 2 + 1] + bv;
                if (relu) { v0 = fmaxf(v0, 0.f); v1 = fmaxf(v1, 0.f); }
                if (stile) {
                    stile[oc * 132 + pxo] = v0;
                    stile[oc * 132 + pxo + 1] = v1;
                }
                if (writeF) {
                    *(float2*)(Yf + (size_t)oc * HW + (size_t)y * Ww + pxo) =
                        make_float2(v0, v1);
                }
                if (writeP) {
                    unsigned short hs0 = bf16u(v0), hs1 = bf16u(v1);
                    unsigned short ls0 = bf16u(v0 - ubf(hs0)), ls1 = bf16u(v1 - ubf(hs1));
                    uint32_t myh = (uint32_t)hs0 | ((uint32_t)hs1 << 16);
                    uint32_t myl = (uint32_t)ls0 | ((uint32_t)ls1 << 16);
                    uint32_t ph = __shfl_down_sync(0xFFFFFFFFu, myh, 4);
                    uint32_t pl = __shfl_down_sync(0xFFFFFFFFu, myl, 4);
                    if (!(qr & 1)) {
                        uint32_t wh0 = (myh & 0xFFFFu) | (ph << 16);
                        uint32_t wh1 = (myh >> 16) | (ph & 0xFFFF0000u);
                        uint32_t wl0 = (myl & 0xFFFFu) | (pl << 16);
                        uint32_t wl1 = (myl >> 16) | (pl & 0xFFFF0000u);
                        size_t w = (size_t)(oc >> 1) * HW + (size_t)y * Ww + pxo;
                        *(uint2*)(Yh + w * 2) = make_uint2(wh0, wh1);
                        *(uint2*)(Yl + w * 2) = make_uint2(wl0, wl1);
                    }
                }
            }
        }
    }
}

__device__ __forceinline__ void load_bregs(const uint32_t* __restrict__ Xrole,
                                           int y, int px, int sub, int ncc, int CI,
                                           uint32_t breg[8][4]) {
    int tap = sub / ncc;
    int ci0 = (sub - tap * ncc) << 6;
    int dy = tap / 3 - 1, dx = tap % 3 - 1;
    int ysrc = y + dy, xsrc = px + dx;
    bool ok = (ysrc >= 0) && (ysrc < Hh) && (xsrc >= 0) && (xsrc < Ww);
    int poff = ysrc * Ww + xsrc;
    int prb = ci0 >> 1;
#pragma unroll
    for (int g = 0; g < 8; g++) {
#pragma unroll
        for (int q = 0; q < 4; q++) {
            int ci = ci0 + (g * 4 + q) * 2;
            breg[g][q] = (ok && ci < CI) ? Xrole[(size_t)(prb + g * 4 + q) * HW + poff] : 0u;
        }
    }
}

// ---------------- HMMA conv: pipelined A + B; HEAD=1 fuses a 1x1 head ----------
#define SMEMH 196608
template <int HEAD>
__global__ void __launch_bounds__(256, 1)
conv_hmma_kernel(const unsigned char* __restrict__ wpack,
                 const uint32_t* __restrict__ Xh, const uint32_t* __restrict__ Xl,
                 const float* __restrict__ bias, float* __restrict__ Yf,
                 unsigned short* __restrict__ Yh, unsigned short* __restrict__ Yl,
                 int CI, int relu, int bias_div, int writeF, int writeP,
                 const float* __restrict__ hw, const float* __restrict__ hbias,
                 float* __restrict__ hout, int headOC) {
    extern __shared__ unsigned char sm[];
    uint32_t aSm = smem_u32(sm);

    int tid = threadIdx.x;
    int y = blockIdx.x;
    int lane = tid & 31, wid = tid >> 5;
    int wm = wid >> 1, wn = wid & 1;
    int mbase = wm * 64;
    int half = mbase >> 7;
    int mrow0 = mbase & 127;
    int nbase = wn * 64;
    int lrow = (lane & 7) + ((lane >> 3) & 1) * 8;
    int lcol16 = (lane >> 4) * 16;
    int role = tid >> 7;
    int px = tid & 127;
    int ncc = (CI + 63) >> 6;
    int nsub = 9 * ncc;
    uint32_t bofs[8];
#pragma unroll
    for (int g = 0; g < 8; g++)
        bofs[g] = (uint32_t)px * 128u + (((uint32_t)g << 4) ^ (((uint32_t)px & 7u) << 4)) +
                  role * 16384u;

    float acc[4][8][4];
#pragma unroll
    for (int a = 0; a < 4; a++)
#pragma unroll
        for (int b = 0; b < 8; b++)
#pragma unroll
            for (int c = 0; c < 4; c++) acc[a][b][c] = 0.f;

    const uint32_t* Xrole = role ? Xl : Xh;

    uint32_t breg[8][4];
    load_bregs(Xrole, y, px, 0, ncc, CI, breg);
    cp_async_tile(aSm, wpack, tid);  // A[0]

    for (int sub = 0; sub < nsub; sub++) {
        uint32_t aA = aSm + (uint32_t)(sub & 1) * 65536u;
        uint32_t aB = aSm + 131072u + (uint32_t)(sub & 1) * 32768u;
#pragma unroll
        for (int g = 0; g < 8; g++)
            *(uint4*)(sm + (aB - aSm) + bofs[g]) = make_uint4(breg[g][0], breg[g][1],
                                                              breg[g][2], breg[g][3]);
        cp_async_wait0();
        __syncthreads();
        if (sub + 1 < nsub) {
            cp_async_tile(aSm + (uint32_t)((sub + 1) & 1) * 65536u,
                          wpack + (size_t)(sub + 1) * 65536, tid);
            load_bregs(Xrole, y, px, sub + 1, ncc, CI, breg);
        }
        mma_substage(aA, aB, half, mrow0, nbase, lrow, lcol16, acc);
    }

    if (HEAD) {
        // all MMA smem reads done before overwriting smem with the output tile
        __syncthreads();
        float* s_hw = (float*)(sm + 180224);  // 4096 floats
#pragma unroll
        for (int i = 0; i < 16; i++) s_hw[tid + i * 256] = hw[tid + i * 256];
        float* stile = (float*)sm;            // [256][132]
        mma_epilogue(acc, mbase, nbase, lane, y, bias, relu, bias_div, 0, 0,
                     (float*)0, (unsigned short*)0, (unsigned short*)0, stile);
        __syncthreads();
        // 1x1 head: out[h][px] = hbias[h] + sum_oc s_hw[oc*16+h] * stile[oc][px]
        float* hpart = (float*)(sm + 163840);  // [15][128]
        float s[15];
#pragma unroll
        for (int h = 0; h < 15; h++) s[h] = 0.f;
        int base = role * 128;
        for (int oc = 0; oc < 128; oc++) {
            float v = stile[(base + oc) * 132 + px];
            const float* wr = s_hw + (base + oc) * 16;
#pragma unroll
            for (int h = 0; h < 15; h++)
                if (h < headOC) s[h] += wr[h] * v;
        }
        if (role) {
            for (int h = 0; h < headOC; h++) hpart[h * 128 + px] = s[h];
        }
        __syncthreads();
        if (!role) {
            for (int h = 0; h < headOC; h++)
                hout[(size_t)h * HW + (size_t)y * Ww + px] =
                    hbias[h] + s[h] + hpart[h * 128 + px];
        }
    } else {
        mma_epilogue(acc, mbase, nbase, lane, y, bias, relu, bias_div, writeF, writeP,
                     Yf, Yh, Yl, (float*)0);
    }
}

// ---------------- deformable HMMA conv (bilinear gather B), pipelined ----------
#define SMEMD 224256
__global__ void __launch_bounds__(256, 1)
conv_deform_kernel(const unsigned char* __restrict__ wpack,
                   const float* __restrict__ feats, const float* __restrict__ refine,
                   const float* __restrict__ bias,
                   unsigned short* __restrict__ Yh, unsigned short* __restrict__ Yl) {
    extern __shared__ unsigned char sm[];
    uint32_t aSm = smem_u32(sm);
    unsigned short* s_idx = (unsigned short*)(sm + 196608);
    float* s_wt = (float*)(sm + 196608 + 9216);

    int tid = threadIdx.x;
    int y = blockIdx.x;
    int lane = tid & 31, wid = tid >> 5;
    int wm = wid >> 1, wn = wid & 1;
    int mbase = wm * 64;
    int half = mbase >> 7;
    int mrow0 = mbase & 127;
    int nbase = wn * 64;
    int lrow = (lane & 7) + ((lane >> 3) & 1) * 8;
    int lcol16 = (lane >> 4) * 16;
    int role = tid >> 7;
    int px = tid & 127;

    for (int e = tid; e < 128 * 9; e += 256) {
        int pxe = e / 9, k = e % 9;
        int p = y * Ww + pxe;
        float axc = refine[p * 5 + 0] * 0.125f;
        float ayc = refine[p * 5 + 1] * 0.125f;
        float aw = refine[p * 5 + 2] * 0.125f;
        float ah = refine[p * 5 + 3] * 0.125f;
        float aa = refine[p * 5 + 4];
        float cs = cosf(aa), sn = sinf(aa);
        float kx = (float)(k % 3 - 1);
        float ky = (float)(k / 3 - 1);
        float ddx = (aw * (1.f / 3.f)) * kx;
        float ddy = (ah * (1.f / 3.f)) * ky;
        float xs = cs * ddx - sn * ddy + axc;
        float ys = sn * ddx + cs * ddy + ayc;
        float x0f = floorf(xs), y0f = floorf(ys);
        float wx1 = xs - x0f, wx0 = 1.f - wx1;
        float wy1 = ys - y0f, wy0 = 1.f - wy1;
        int x0 = (int)x0f, y0 = (int)y0f;
#pragma unroll
        for (int c = 0; c < 4; c++) {
            int xi = x0 + (c & 1);
            int yi = y0 + (c >> 1);
            float ww = ((c & 1) ? wx1 : wx0) * ((c >> 1) ? wy1 : wy0);
            bool valid = (xi >= 0 && xi < Ww && yi >= 0 && yi < Hh);
            int xc = min(max(xi, 0), Ww - 1);
            int yc = min(max(yi, 0), Hh - 1);
            s_idx[(k * 4 + c) * 128 + pxe] = (unsigned short)(yc * Ww + xc);
            s_wt[(k * 4 + c) * 128 + pxe] = valid ? ww : 0.f;
        }
    }

    float acc[4][8][4];
#pragma unroll
    for (int a = 0; a < 4; a++)
#pragma unroll
        for (int b = 0; b < 8; b++)
#pragma unroll
            for (int c = 0; c < 4; c++) acc[a][b][c] = 0.f;

    cp_async_tile(aSm, wpack, tid);
    __syncthreads();

    uint32_t hv[16], lv[16];
    {
        int tap = 0, ci0 = 0;
        int I0 = s_idx[(tap * 4 + 0) * 128 + px];
        int I1 = s_idx[(tap * 4 + 1) * 128 + px];
        int I2 = s_idx[(tap * 4 + 2) * 128 + px];
        int I3 = s_idx[(tap * 4 + 3) * 128 + px];
        float W0 = s_wt[(tap * 4 + 0) * 128 + px];
        float W1 = s_wt[(tap * 4 + 1) * 128 + px];
        float W2 = s_wt[(tap * 4 + 2) * 128 + px];
        float W3 = s_wt[(tap * 4 + 3) * 128 + px];
        int cbase = ci0 + role * 32;
#pragma unroll
        for (int j = 0; j < 16; j++) {
            const float* f0 = feats + (size_t)(cbase + j * 2) * HW;
            const float* f1 = feats + (size_t)(cbase + j * 2 + 1) * HW;
            float v0 = f0[I0] * W0 + f0[I1] * W1 + f0[I2] * W2 + f0[I3] * W3;
            float v1 = f1[I0] * W0 + f1[I1] * W1 + f1[I2] * W2 + f1[I3] * W3;
            unsigned short h0 = bf16u(v0), h1 = bf16u(v1);
            hv[j] = (uint32_t)h0 | ((uint32_t)h1 << 16);
            lv[j] = (uint32_t)bf16u(v0 - ubf(h0)) | ((uint32_t)bf16u(v1 - ubf(h1)) << 16);
        }
    }

    for (int sub = 0; sub < 36; sub++) {
        uint32_t aA = aSm + (uint32_t)(sub & 1) * 65536u;
        uint32_t aB = aSm + 131072u + (uint32_t)(sub & 1) * 32768u;
#pragma unroll
        for (int gg = 0; gg < 4; gg++) {
            uint32_t ofs = (uint32_t)px * 128u +
                           (((uint32_t)(role * 4 + gg) << 4) ^ (((uint32_t)px & 7u) << 4));
            *(uint4*)(sm + (aB - aSm) + ofs) = *(uint4*)&hv[gg * 4];
            *(uint4*)(sm + (aB - aSm) + 16384 + ofs) = *(uint4*)&lv[gg * 4];
        }
        cp_async_wait0();
        __syncthreads();
        if (sub + 1 < 36) {
            cp_async_tile(aSm + (uint32_t)((sub + 1) & 1) * 65536u,
                          wpack + (size_t)(sub + 1) * 65536, tid);
            int tap = (sub + 1) >> 2;
            int ci0 = ((sub + 1) & 3) << 6;
            int I0 = s_idx[(tap * 4 + 0) * 128 + px];
            int I1 = s_idx[(tap * 4 + 1) * 128 + px];
            int I2 = s_idx[(tap * 4 + 2) * 128 + px];
            int I3 = s_idx[(tap * 4 + 3) * 128 + px];
            float W0 = s_wt[(tap * 4 + 0) * 128 + px];
            float W1 = s_wt[(tap * 4 + 1) * 128 + px];
            float W2 = s_wt[(tap * 4 + 2) * 128 + px];
            float W3 = s_wt[(tap * 4 + 3) * 128 + px];
            int cbase = ci0 + role * 32;
#pragma unroll
            for (int j = 0; j < 16; j++) {
                const float* f0 = feats + (size_t)(cbase + j * 2) * HW;
                const float* f1 = feats + (size_t)(cbase + j * 2 + 1) * HW;
                float v0 = f0[I0] * W0 + f0[I1] * W1 + f0[I2] * W2 + f0[I3] * W3;
                float v1 = f1[I0] * W0 + f1[I1] * W1 + f1[I2] * W2 + f1[I3] * W3;
                unsigned short h0 = bf16u(v0), h1 = bf16u(v1);
                hv[j] = (uint32_t)h0 | ((uint32_t)h1 << 16);
                lv[j] = (uint32_t)bf16u(v0 - ubf(h0)) | ((uint32_t)bf16u(v1 - ubf(h1)) << 16);
            }
        }
        mma_substage(aA, aB, half, mrow0, nbase, lrow, lcol16, acc);
    }

    mma_epilogue(acc, mbase, nbase, lane, y, bias, 1, 1, 0, 1, (float*)0, Yh, Yl, (float*)0);
}

// ---------------- head partial conv (one 3x3 tap per block, ODM heads) ----------
__global__ void __launch_bounds__(128, 4)
head_part_kernel(const float* __restrict__ wt, const float* __restrict__ X,
                 float* __restrict__ part, int CI, int NK) {
    __shared__ float Ws[8][16];
    __shared__ float Xs[8][128];

    int y = blockIdx.x;
    int k = blockIdx.y;
    int tid = threadIdx.x;
    int tx = tid & 31;
    int ty = tid >> 5;

    float acc[4][4];
#pragma unroll
    for (int i = 0; i < 4; i++)
#pragma unroll
        for (int j = 0; j < 4; j++) acc[i][j] = 0.f;

    int dy = (NK == 9) ? (k / 3 - 1) : 0;
    int dx = (NK == 9) ? (k % 3 - 1) : 0;
    int yy = y + dy;
    bool rowok = (yy >= 0 && yy < Hh);

    for (int ci0 = 0; ci0 < CI; ci0 += 8) {
        {
            int kk = tid >> 4;
            int m = tid & 15;
            Ws[kk][m] = wt[((size_t)(k * CI + ci0 + kk)) * 16 + m];
        }
        {
            int kk = tid >> 4;
            int lanex = tid & 15;
            const float* xrow = X + (size_t)(ci0 + kk) * HW + yy * Ww;
#pragma unroll
            for (int j = 0; j < 8; j++) {
                int n = lanex + 16 * j;
                int xx = n + dx;
                float v = 0.f;
                if (rowok && xx >= 0 && xx < Ww) v = xrow[xx];
                Xs[kk][n] = v;
            }
        }
        __syncthreads();
#pragma unroll
        for (int kk = 0; kk < 8; kk++) {
            float a[4], b[4];
            *(float4*)a = *(const float4*)&Ws[kk][ty * 4];
            *(float4*)b = *(const float4*)&Xs[kk][tx * 4];
#pragma unroll
            for (int i = 0; i < 4; i++)
#pragma unroll
                for (int j = 0; j < 4; j++) acc[i][j] += a[i] * b[j];
        }
        __syncthreads();
    }

#pragma unroll
    for (int i = 0; i < 4; i++) {
        int m = ty * 4 + i;
#pragma unroll
        for (int j = 0; j < 4; j++) {
            int n = tx * 4 + j;
            part[((size_t)k * 16 + m) * HW + (size_t)y * Ww + n] = acc[i][j];
        }
    }
}

__global__ void head_reduce_kernel(const float* __restrict__ part,
                                   const float* __restrict__ bias,
                                   float* __restrict__ Y, int OC, int NK) {
    int idx = blockIdx.x * blockDim.x + threadIdx.x;
    if (idx >= OC * HW) return;
    int m = idx / HW, p = idx - m * HW;
    float s = bias[m];
    for (int t = 0; t < NK; t++) s += part[((size_t)t * 16 + m) * HW + p];
    Y[(size_t)m * HW + p] = s;
}

// ---------------- anchors + rbox decode ----------------
__global__ void decode_kernel(const float* __restrict__ bbox,
                              float* __restrict__ anchors_out,
                              float* __restrict__ refine_out) {
    int p = blockIdx.x * blockDim.x + threadIdx.x;
    if (p >= HW) return;
    int x = p & 127, yv = p >> 7;
    float ax = x * 8.f + 3.5f;
    float ay = yv * 8.f + 3.5f;
    anchors_out[p * 5 + 0] = ax;
    anchors_out[p * 5 + 1] = ay;
    anchors_out[p * 5 + 2] = 32.f;
    anchors_out[p * 5 + 3] = 32.f;
    anchors_out[p * 5 + 4] = 0.f;

    float dx = bbox[p];
    float dyv = bbox[HW + p];
    float dw = bbox[2 * HW + p];
    float dh = bbox[3 * HW + p];
    float dt = bbox[4 * HW + p];
    const float MR = 13.815510557964274f;
    dw = fminf(fmaxf(dw, -MR), MR);
    dh = fminf(fmaxf(dh, -MR), MR);
    float gx = dx * 32.f + ax;
    float gy = dyv * 32.f + ay;
    float gw = 32.f * expf(dw);
    float gh = 32.f * expf(dh);
    const float PI = 3.14159265358979323846f;
    float r = fmodf(dt + PI * 0.25f, PI);
    if (r < 0.f) r += PI;
    float ga = r - PI * 0.25f;
    refine_out[p * 5 + 0] = gx;
    refine_out[p * 5 + 1] = gy;
    refine_out[p * 5 + 2] = gw;
    refine_out[p * 5 + 3] = gh;
    refine_out[p * 5 + 4] = ga;
}

// ---------------- rotation-invariant max pooling on pair tensors ----------------
__global__ void maxpool8_kernel(const uint32_t* __restrict__ oh,
                                const uint32_t* __restrict__ ol,
                                unsigned short* __restrict__ ph,
                                unsigned short* __restrict__ pl) {
    int p = blockIdx.x * blockDim.x + threadIdx.x;
    int i = blockIdx.y;
    if (p >= HW) return;
    float m = -1e30f;
#pragma unroll
    for (int r2 = 0; r2 < 4; r2++) {
        size_t w = (size_t)(i * 4 + r2) * HW + p;
        uint32_t wh = oh[w], wl = ol[w];
        float v0 = half_of(wh, 0) + half_of(wl, 0);
        float v1 = half_of(wh, 1) + half_of(wl, 1);
        m = fmaxf(m, fmaxf(v0, v1));
    }
    size_t wo = ((size_t)(i >> 1) * HW + p) * 2 + (i & 1);
    unsigned short hb = bf16u(m);
    ph[wo] = hb;
    pl[wo] = bf16u(m - ubf(hb));
}

// ---------------- host orchestration ----------------
extern "C" void kernel_launch(void* const* d_in, const int* in_sizes, int n_in,
                              void* d_out, int out_size) {
    (void)in_sizes; (void)n_in; (void)out_size;

    const float* feats = (const float*)d_in[0];
    const float* fam_reg_w0 = (const float*)d_in[1];
    const float* fam_reg_b0 = (const float*)d_in[2];
    const float* fam_reg_w1 = (const float*)d_in[3];
    const float* fam_reg_b1 = (const float*)d_in[4];
    const float* fam_reg_hw = (const float*)d_in[5];
    const float* fam_reg_hb = (const float*)d_in[6];
    const float* fam_cls_w0 = (const float*)d_in[7];
    const float* fam_cls_b0 = (const float*)d_in[8];
    const float* fam_cls_w1 = (const float*)d_in[9];
    const float* fam_cls_b1 = (const float*)d_in[10];
    const float* fam_cls_hw = (const float*)d_in[11];
    const float* fam_cls_hb = (const float*)d_in[12];
    const float* align_w = (const float*)d_in[13];
    const float* align_b = (const float*)d_in[14];
    const float* or_w = (const float*)d_in[15];
    const float* or_b = (const float*)d_in[16];
    const float* odm_reg_w0 = (const float*)d_in[17];
    const float* odm_reg_b0 = (const float*)d_in[18];
    const float* odm_reg_w1 = (const float*)d_in[19];
    const float* odm_reg_b1 = (const float*)d_in[20];
    const float* odm_reg_hw = (const float*)d_in[21];
    const float* odm_reg_hb = (const float*)d_in[22];
    const float* odm_cls_w0 = (const float*)d_in[23];
    const float* odm_cls_b0 = (const float*)d_in[24];
    const float* odm_cls_w1 = (const float*)d_in[25];
    const float* odm_cls_b1 = (const float*)d_in[26];
    const float* odm_cls_hw = (const float*)d_in[27];
    const float* odm_cls_hb = (const float*)d_in[28];

    float* out = (float*)d_out;
    float* o_famcls = out;
    float* o_fambbox = out + 245760;
    float* o_odmcls = out + 327680;
    float* o_odmbbox = out + 573440;
    float* o_anchors = out + 655360;
    float* o_refine = out + 737280;

    float *b1, *b2, *wts, *hd, *hd2;
    unsigned char* wp;
    uint32_t *p0h, *p0l, *p1h, *p1l, *p2h, *p2l, *p3h, *p3l, *pdh, *pdl;
    cudaGetSymbolAddress((void**)&b1, g_b1);
    cudaGetSymbolAddress((void**)&b2, g_b2);
    cudaGetSymbolAddress((void**)&hd, g_head);
    cudaGetSymbolAddress((void**)&hd2, g_head2);
    cudaGetSymbolAddress((void**)&wts, g_wt_small);
    cudaGetSymbolAddress((void**)&wp, g_wpack);
    cudaGetSymbolAddress((void**)&p0h, g_p0h);
    cudaGetSymbolAddress((void**)&p0l, g_p0l);
    cudaGetSymbolAddress((void**)&p1h, g_p1h);
    cudaGetSymbolAddress((void**)&p1l, g_p1l);
    cudaGetSymbolAddress((void**)&p2h, g_p2h);
    cudaGetSymbolAddress((void**)&p2l, g_p2l);
    cudaGetSymbolAddress((void**)&p3h, g_p3h);
    cudaGetSymbolAddress((void**)&p3l, g_p3l);
    cudaGetSymbolAddress((void**)&pdh, g_pdh);
    cudaGetSymbolAddress((void**)&pdl, g_pdl);

    cudaFuncSetAttribute(conv_hmma_kernel<0>, cudaFuncAttributeMaxDynamicSharedMemorySize, SMEMH);
    cudaFuncSetAttribute(conv_hmma_kernel<1>, cudaFuncAttributeMaxDynamicSharedMemorySize, SMEMH);
    cudaFuncSetAttribute(conv_deform_kernel, cudaFuncAttributeMaxDynamicSharedMemorySize, SMEMD);

    cudaStream_t s1;
    cudaEvent_t ev0, ev1, ev2, ev3;
    cudaStreamCreateWithFlags(&s1, cudaStreamNonBlocking);
    cudaEventCreateWithFlags(&ev0, cudaEventDisableTiming);
    cudaEventCreateWithFlags(&ev1, cudaEventDisableTiming);
    cudaEventCreateWithFlags(&ev2, cudaEventDisableTiming);
    cudaEventCreateWithFlags(&ev3, cudaEventDisableTiming);

    const size_t SLOT = 36 * 65536;

    // ---- prologue (stream 0): repacks first (ncu skip alignment), cvt last ----
    {
        WPtrs P;
        P.w[0] = fam_reg_w0; P.w[1] = fam_reg_w1; P.w[2] = fam_cls_w0; P.w[3] = fam_cls_w1;
        P.w[4] = align_w; P.w[5] = odm_cls_w1; P.w[6] = odm_reg_w0; P.w[7] = odm_reg_w1;
        P.w[8] = odm_cls_w0;
        repack_all_kernel<<<(8 * 36 * 16384 + 9 * 16384 + 255) / 256, 256>>>(P, wp);
    }
    repack_or_tc_kernel<<<2304, 256>>>(or_w, wp);
    repack_heads_kernel<<<320, 256>>>(fam_reg_hw, fam_cls_hw, odm_cls_hw, odm_reg_hw, wts);
    cvt_pair_kernel<<<8192, 256>>>(feats, p0h, p0l, 128 * HW);

    // ---- fork 1: FAM reg (s0) || FAM cls (s1) ----
    cudaEventRecord(ev0, 0);
    cudaStreamWaitEvent(s1, ev0, 0);

    // s0: FAM reg: p0 -> p1 pair; p1 -> fused 1x1 head -> fambbox; decode; deform
    conv_hmma_kernel<0><<<128, 256, SMEMH>>>(wp + 0 * SLOT, p0h, p0l, fam_reg_b0, (float*)0,
                                             (unsigned short*)p1h, (unsigned short*)p1l,
                                             256, 1, 1, 0, 1,
                                             (float*)0, (float*)0, (float*)0, 0);
    conv_hmma_kernel<1><<<128, 256, SMEMH>>>(wp + 1 * SLOT, p1h, p1l, fam_reg_b1, (float*)0,
                                             (unsigned short*)0, (unsigned short*)0,
                                             256, 1, 1, 0, 0,
                                             wts + 0, fam_reg_hb, o_fambbox, 5);
    decode_kernel<<<HW / 256, 256>>>(o_fambbox, o_anchors, o_refine);
    conv_deform_kernel<<<128, 256, SMEMD>>>(wp + 4 * SLOT, feats, o_refine, align_b,
                                            (unsigned short*)p1h, (unsigned short*)p1l);

    // s1: FAM cls: p0 -> p2 pair; p2 -> fused 1x1 head -> famcls
    conv_hmma_kernel<0><<<128, 256, SMEMH, s1>>>(wp + 2 * SLOT, p0h, p0l, fam_cls_b0, (float*)0,
                                                 (unsigned short*)p2h, (unsigned short*)p2l,
                                                 256, 1, 1, 0, 1,
                                                 (float*)0, (float*)0, (float*)0, 0);
    conv_hmma_kernel<1><<<128, 256, SMEMH, s1>>>(wp + 3 * SLOT, p2h, p2l, fam_cls_b1, (float*)0,
                                                 (unsigned short*)0, (unsigned short*)0,
                                                 256, 1, 1, 0, 0,
                                                 wts + 4096, fam_cls_hb, o_famcls, 15);

    // join 1 (OR overwrites p2, which FAM cls reads)
    cudaEventRecord(ev1, s1);
    cudaStreamWaitEvent(0, ev1, 0);

    // ---- middle (s0): OR conv -> p2, pool -> pd ----
    conv_hmma_kernel<0><<<128, 256, SMEMH>>>(wp + 8 * SLOT, p1h, p1l, or_b, (float*)0,
                                             (unsigned short*)p2h, (unsigned short*)p2l,
                                             256, 0, 8, 0, 1,
                                             (float*)0, (float*)0, (float*)0, 0);
    {
        dim3 g(HW / 256, 32);
        maxpool8_kernel<<<g, 256>>>(p2h, p2l, (unsigned short*)pdh, (unsigned short*)pdl);
    }

    // ---- fork 2: ODM cls (s0) || ODM reg (s1) ----
    cudaEventRecord(ev2, 0);
    cudaStreamWaitEvent(s1, ev2, 0);

    // s0: ODM cls: pd -> p3 pair, p3 -> b1 fp32, 3x3 head
    conv_hmma_kernel<0><<<128, 256, SMEMH>>>(wp + 9 * SLOT, pdh, pdl, odm_cls_b0, (float*)0,
                                             (unsigned short*)p3h, (unsigned short*)p3l,
                                             32, 1, 1, 0, 1,
                                             (float*)0, (float*)0, (float*)0, 0);
    conv_hmma_kernel<0><<<128, 256, SMEMH>>>(wp + 5 * SLOT, p3h, p3l, odm_cls_b1, b1,
                                             (unsigned short*)0, (unsigned short*)0,
                                             256, 1, 1, 1, 0,
                                             (float*)0, (float*)0, (float*)0, 0);
    head_part_kernel<<<dim3(128, 9), 128>>>(wts + 8192, b1, hd, 256, 9);
    head_reduce_kernel<<<(15 * HW + 255) / 256, 256>>>(hd, odm_cls_hb, o_odmcls, 15, 9);

    // s1: ODM reg: p2 -> p0 pair, p0 -> b2 fp32, 3x3 head
    conv_hmma_kernel<0><<<128, 256, SMEMH, s1>>>(wp + 6 * SLOT, p2h, p2l, odm_reg_b0, (float*)0,
                                                 (unsigned short*)p0h, (unsigned short*)p0l,
                                                 256, 1, 1, 0, 1,
                                                 (float*)0, (float*)0, (float*)0, 0);
    conv_hmma_kernel<0><<<128, 256, SMEMH, s1>>>(wp + 7 * SLOT, p0h, p0l, odm_reg_b1, b2,
                                                 (unsigned short*)0, (unsigned short*)0,
                                                 256, 1, 1, 1, 0,
                                                 (float*)0, (float*)0, (float*)0, 0);
    head_part_kernel<<<dim3(128, 9), 128, 0, s1>>>(wts + 45056, b2, hd2, 256, 9);
    head_reduce_kernel<<<(5 * HW + 255) / 256, 256, 0, s1>>>(hd2, odm_reg_hb, o_odmbbox, 5, 9);

    // join 2
    cudaEventRecord(ev3, s1);
    cudaStreamWaitEvent(0, ev3, 0);
}

// round 15
// speedup vs baseline: 1.4929x; 1.4336x over previous
#include <cuda_runtime.h>
#include <cuda_bf16.h>
#include <cuda_fp16.h>
#include <math.h>
#include <stdint.h>

#define Hh 128
#define Ww 128
#define HW 16384
#define CC 256

// ---------------- scratch (static __device__, no allocs) ----------------
__device__ float g_b1[CC * HW];
__device__ float g_b2[CC * HW];
__device__ float g_head[9 * 16 * HW];
__device__ float g_head2[9 * 16 * HW];
__device__ float g_wt_small[81920];
__device__ unsigned char g_wpack[333 * 65536];
// pair tensors: u32 word = (fp16 ch 2m) | (fp16 ch 2m+1 << 16), index m*HW + p
__device__ uint32_t g_p0h[128 * HW];
__device__ uint32_t g_p1h[128 * HW];
__device__ uint32_t g_p2h[128 * HW];
__device__ uint32_t g_p3h[128 * HW];
__device__ uint32_t g_pdh[16 * HW];

__constant__ int c_ring[8] = {0, 1, 2, 5, 8, 7, 6, 3};

struct WPtrs {
    const float* w[9];
};

// ---------------- helpers ----------------
__device__ __forceinline__ uint32_t smem_u32(const void* p) {
    uint32_t a;
    asm("{ .reg .u64 t; cvta.to.shared.u64 t, %1; cvt.u32.u64 %0, t; }" : "=r"(a) : "l"(p));
    return a;
}
__device__ __forceinline__ void ldm4(uint32_t* r, uint32_t addr) {
    asm volatile("ldmatrix.sync.aligned.m8n8.x4.shared.b16 {%0,%1,%2,%3}, [%4];"
                 : "=r"(r[0]), "=r"(r[1]), "=r"(r[2]), "=r"(r[3]) : "r"(addr));
}
__device__ __forceinline__ void mma_f16(float* c, const uint32_t* a, uint32_t b0, uint32_t b1) {
    asm volatile(
        "mma.sync.aligned.m16n8k16.row.col.f32.f16.f16.f32 "
        "{%0,%1,%2,%3}, {%4,%5,%6,%7}, {%8,%9}, {%0,%1,%2,%3};"
        : "+f"(c[0]), "+f"(c[1]), "+f"(c[2]), "+f"(c[3])
        : "r"(a[0]), "r"(a[1]), "r"(a[2]), "r"(a[3]), "r"(b0), "r"(b1));
}
__device__ __forceinline__ unsigned short f16u(float v) {
    __half h = __float2half(v);
    return *(unsigned short*)&h;
}
__device__ __forceinline__ float uf16(unsigned short u) {
    __half h = *(__half*)&u;
    return __half2float(h);
}
__device__ __forceinline__ float half_of(uint32_t w, int hi) {
    return uf16((unsigned short)(hi ? (w >> 16) : (w & 0xFFFF)));
}
__device__ __forceinline__ void cp_async_tile(uint32_t dst, const unsigned char* src, int tid) {
#pragma unroll
    for (int i = 0; i < 16; i++) {
        asm volatile("cp.async.cg.shared.global [%0], [%1], 16;"
                     :: "r"(dst + (uint32_t)(tid + i * 256) * 16),
                        "l"(src + (size_t)(tid + i * 256) * 16) : "memory");
    }
    asm volatile("cp.async.commit_group;" ::: "memory");
}
__device__ __forceinline__ void cp_async_wait0() {
    asm volatile("cp.async.wait_group 0;" ::: "memory");
}

// ---------------- consolidated weight repacks (fp16 hi/lo) ----------------
__global__ void repack_all_kernel(WPtrs P, unsigned char* __restrict__ wp) {
    const int BIG = 8 * 36 * 16384;
    int idx = blockIdx.x * blockDim.x + threadIdx.x;
    if (idx < BIG) {
        int slot = idx / (36 * 16384);
        int r = idx - slot * (36 * 16384);
        int kc = r & 63;
        int oc = (r >> 6) & 255;
        int sub = r >> 14;
        int tap = sub >> 2, cc2 = sub & 3;
        int ci = (cc2 << 6) + kc;
        float v = P.w[slot][((size_t)oc * 256 + ci) * 9 + tap];
        unsigned short hb = f16u(v);
        unsigned short lb = f16u(v - uf16(hb));
        int half = oc >> 7, ocl = oc & 127;
        uint32_t ofs = (uint32_t)ocl * 128u + (((uint32_t)kc * 2u) ^ (((uint32_t)ocl & 7u) << 4));
        size_t base = (size_t)(slot * 36 + sub) * 65536 + (size_t)(half * 2) * 16384;
        *(unsigned short*)(wp + base + ofs) = hb;
        *(unsigned short*)(wp + base + 16384 + ofs) = lb;
    } else {
        int r = idx - BIG;
        if (r >= 9 * 16384) return;
        int kc = r & 63;
        int oc = (r >> 6) & 255;
        int tap = r >> 14;
        int ci = kc;
        float v = (ci < 32) ? P.w[8][((size_t)oc * 32 + ci) * 9 + tap] : 0.f;
        unsigned short hb = f16u(v);
        unsigned short lb = f16u(v - uf16(hb));
        int half = oc >> 7, ocl = oc & 127;
        uint32_t ofs = (uint32_t)ocl * 128u + (((uint32_t)kc * 2u) ^ (((uint32_t)ocl & 7u) << 4));
        size_t base = (size_t)(324 + tap) * 65536 + (size_t)(half * 2) * 16384;
        *(unsigned short*)(wp + base + ofs) = hb;
        *(unsigned short*)(wp + base + 16384 + ofs) = lb;
    }
}

// OR-conv: rotated ring source tap, 36 subs at 288*65536
__global__ void repack_or_tc_kernel(const float* __restrict__ w,
                                    unsigned char* __restrict__ wp) {
    int idx = blockIdx.x * blockDim.x + threadIdx.x;
    if (idx >= 36 * 16384) return;
    int kc = idx & 63;
    int oc = (idx >> 6) & 255;
    int sub = idx >> 14;
    int tap = sub >> 2, cc2 = sub & 3;
    int ci = (cc2 << 6) + kc;
    int o = oc >> 3, r = oc & 7;
    int s;
    if (tap == 4) {
        s = 4;
    } else {
        int j = 0;
#pragma unroll
        for (int t = 0; t < 8; t++)
            if (c_ring[t] == tap) j = t;
        s = c_ring[(j - r + 8) & 7];
    }
    float v = w[((size_t)o * CC + ci) * 9 + s];
    unsigned short hb = f16u(v);
    unsigned short lb = f16u(v - uf16(hb));
    int half = oc >> 7, ocl = oc & 127;
    uint32_t ofs = (uint32_t)ocl * 128u + (((uint32_t)kc * 2u) ^ (((uint32_t)ocl & 7u) << 4));
    size_t base = (size_t)(288 + sub) * 65536 + (size_t)(half * 2) * 16384;
    *(unsigned short*)(wp + base + ofs) = hb;
    *(unsigned short*)(wp + base + 16384 + ofs) = lb;
}

// head weights layout wt[k*4096 + ci*16 + oc]
__global__ void repack_heads_kernel(const float* __restrict__ w0, const float* __restrict__ w1,
                                    const float* __restrict__ w2, const float* __restrict__ w3,
                                    float* __restrict__ wt) {
    int idx = blockIdx.x * blockDim.x + threadIdx.x;
    if (idx >= 81920) return;
    const float* w;
    int OC, NK, r;
    if (idx < 4096) { w = w0; OC = 5; NK = 1; r = idx; }
    else if (idx < 8192) { w = w1; OC = 15; NK = 1; r = idx - 4096; }
    else if (idx < 45056) { w = w2; OC = 15; NK = 9; r = idx - 8192; }
    else { w = w3; OC = 5; NK = 9; r = idx - 45056; }
    int oc = r & 15;
    int ci = (r >> 4) & 255;
    int k = r >> 12;
    wt[idx] = (oc < OC) ? w[((size_t)oc * 256 + ci) * NK + k] : 0.f;
}

// ---------------- fp32 [C][HW] -> fp16 pair-interleaved u32 words ----------------
__global__ void cvt_pair_kernel(const float* __restrict__ x,
                                uint32_t* __restrict__ h, int nwords) {
    int i = blockIdx.x * blockDim.x + threadIdx.x;
    if (i >= nwords) return;
    int cp = i >> 14, p = i & 16383;
    float v0 = x[(size_t)(cp * 2) * HW + p];
    float v1 = x[(size_t)(cp * 2 + 1) * HW + p];
    h[i] = (uint32_t)f16u(v0) | ((uint32_t)f16u(v1) << 16);
}

// ---------------- shared MMA core pieces (2-GEMM: Ah*B + Al*B) ----------------
__device__ __forceinline__ void mma_substage(uint32_t aA, uint32_t aB, int half,
                                             int mrow0, int nbase, int lrow, int lcol16,
                                             float acc[4][8][4]) {
#pragma unroll
    for (int ks = 0; ks < 4; ks++) {
        int kb = ks * 32;
        uint32_t Ah[4][4], Al[4][4];
#pragma unroll
        for (int mt = 0; mt < 4; mt++) {
            int row = mrow0 + mt * 16 + lrow;
            uint32_t roff = (uint32_t)row * 128u +
                            (((uint32_t)(kb + lcol16)) ^ (((uint32_t)row & 7u) << 4));
            ldm4(Ah[mt], aA + (half * 2 + 0) * 16384 + roff);
            ldm4(Al[mt], aA + (half * 2 + 1) * 16384 + roff);
        }
        uint32_t Bh[4][4];
#pragma unroll
        for (int nt = 0; nt < 4; nt++) {
            int row = nbase + nt * 16 + lrow;
            uint32_t roff = (uint32_t)row * 128u +
                            (((uint32_t)(kb + lcol16)) ^ (((uint32_t)row & 7u) << 4));
            ldm4(Bh[nt], aB + roff);
        }
#pragma unroll
        for (int mt = 0; mt < 4; mt++)
#pragma unroll
            for (int nt = 0; nt < 4; nt++) {
                mma_f16(acc[mt][nt * 2 + 0], Ah[mt], Bh[nt][0], Bh[nt][2]);
                mma_f16(acc[mt][nt * 2 + 0], Al[mt], Bh[nt][0], Bh[nt][2]);
                mma_f16(acc[mt][nt * 2 + 1], Ah[mt], Bh[nt][1], Bh[nt][3]);
                mma_f16(acc[mt][nt * 2 + 1], Al[mt], Bh[nt][1], Bh[nt][3]);
            }
    }
}

// epilogue: optional fp32 write, shfl-packed fp16 write, optional smem tile dump
__device__ __forceinline__ void mma_epilogue(float acc[4][8][4], int mbase, int nbase,
                                             int lane, int y, const float* bias,
                                             int relu, int bias_div, int writeF, int writeP,
                                             float* Yf, unsigned short* Yh, float* stile) {
    int qr = lane >> 2, qc = lane & 3;
#pragma unroll
    for (int mt = 0; mt < 4; mt++) {
#pragma unroll
        for (int nf = 0; nf < 8; nf++) {
#pragma unroll
            for (int p = 0; p < 2; p++) {
                int oc = mbase + mt * 16 + qr + p * 8;
                int pxo = nbase + nf * 8 + qc * 2;
                float bv = bias[oc / bias_div];
                float v0 = acc[mt][nf][p * 2 + 0] + bv;
                float v1 = acc[mt][nf][p * 2 + 1] + bv;
                if (relu) { v0 = fmaxf(v0, 0.f); v1 = fmaxf(v1, 0.f); }
                if (stile) {
                    stile[oc * 132 + pxo] = v0;
                    stile[oc * 132 + pxo + 1] = v1;
                }
                if (writeF) {
                    *(float2*)(Yf + (size_t)oc * HW + (size_t)y * Ww + pxo) =
                        make_float2(v0, v1);
                }
                if (writeP) {
                    uint32_t myh = (uint32_t)f16u(v0) | ((uint32_t)f16u(v1) << 16);
                    uint32_t ph = __shfl_down_sync(0xFFFFFFFFu, myh, 4);
                    if (!(qr & 1)) {
                        uint32_t wh0 = (myh & 0xFFFFu) | (ph << 16);
                        uint32_t wh1 = (myh >> 16) | (ph & 0xFFFF0000u);
                        size_t w = (size_t)(oc >> 1) * HW + (size_t)y * Ww + pxo;
                        *(uint2*)(Yh + w * 2) = make_uint2(wh0, wh1);
                    }
                }
            }
        }
    }
}

// B-regs: 4 groups per thread (role picks groups 0-3 or 4-7)
__device__ __forceinline__ void load_bregs(const uint32_t* __restrict__ X,
                                           int y, int px, int role, int sub, int ncc, int CI,
                                           uint32_t breg[4][4]) {
    int tap = sub / ncc;
    int ci0 = (sub - tap * ncc) << 6;
    int dy = tap / 3 - 1, dx = tap % 3 - 1;
    int ysrc = y + dy, xsrc = px + dx;
    bool ok = (ysrc >= 0) && (ysrc < Hh) && (xsrc >= 0) && (xsrc < Ww);
    int poff = ysrc * Ww + xsrc;
    int prb = ci0 >> 1;
#pragma unroll
    for (int g = 0; g < 4; g++) {
        int ga = role * 4 + g;
#pragma unroll
        for (int q = 0; q < 4; q++) {
            int ci = ci0 + (ga * 4 + q) * 2;
            breg[g][q] = (ok && ci < CI) ? X[(size_t)(prb + ga * 4 + q) * HW + poff] : 0u;
        }
    }
}

// ---------------- HMMA conv: pipelined A + B; HEAD=1 fuses a 1x1 head ----------
#define SMEMH 163840
template <int HEAD>
__global__ void __launch_bounds__(256, 1)
conv_hmma_kernel(const unsigned char* __restrict__ wpack,
                 const uint32_t* __restrict__ Xh,
                 const float* __restrict__ bias, float* __restrict__ Yf,
                 unsigned short* __restrict__ Yh,
                 int CI, int relu, int bias_div, int writeF, int writeP,
                 const float* __restrict__ hw, const float* __restrict__ hbias,
                 float* __restrict__ hout, int headOC) {
    extern __shared__ unsigned char sm[];
    uint32_t aSm = smem_u32(sm);

    int tid = threadIdx.x;
    int y = blockIdx.x;
    int lane = tid & 31, wid = tid >> 5;
    int wm = wid >> 1, wn = wid & 1;
    int mbase = wm * 64;
    int half = mbase >> 7;
    int mrow0 = mbase & 127;
    int nbase = wn * 64;
    int lrow = (lane & 7) + ((lane >> 3) & 1) * 8;
    int lcol16 = (lane >> 4) * 16;
    int role = tid >> 7;
    int px = tid & 127;
    int ncc = (CI + 63) >> 6;
    int nsub = 9 * ncc;
    uint32_t bofs[4];
#pragma unroll
    for (int g = 0; g < 4; g++) {
        int ga = role * 4 + g;
        bofs[g] = (uint32_t)px * 128u + (((uint32_t)ga << 4) ^ (((uint32_t)px & 7u) << 4));
    }

    float acc[4][8][4];
#pragma unroll
    for (int a = 0; a < 4; a++)
#pragma unroll
        for (int b = 0; b < 8; b++)
#pragma unroll
            for (int c = 0; c < 4; c++) acc[a][b][c] = 0.f;

    uint32_t breg[4][4];
    load_bregs(Xh, y, px, role, 0, ncc, CI, breg);
    cp_async_tile(aSm, wpack, tid);  // A[0]

    for (int sub = 0; sub < nsub; sub++) {
        uint32_t aA = aSm + (uint32_t)(sub & 1) * 65536u;
        uint32_t aB = aSm + 131072u + (uint32_t)(sub & 1) * 16384u;
#pragma unroll
        for (int g = 0; g < 4; g++)
            *(uint4*)(sm + (aB - aSm) + bofs[g]) = make_uint4(breg[g][0], breg[g][1],
                                                              breg[g][2], breg[g][3]);
        cp_async_wait0();
        __syncthreads();
        if (sub + 1 < nsub) {
            cp_async_tile(aSm + (uint32_t)((sub + 1) & 1) * 65536u,
                          wpack + (size_t)(sub + 1) * 65536, tid);
            load_bregs(Xh, y, px, role, sub + 1, ncc, CI, breg);
        }
        mma_substage(aA, aB, half, mrow0, nbase, lrow, lcol16, acc);
    }

    if (HEAD) {
        __syncthreads();  // all MMA smem reads done before tile dump
        float* s_hw = (float*)(sm + 135168);   // 4096 floats
#pragma unroll
        for (int i = 0; i < 16; i++) s_hw[tid + i * 256] = hw[tid + i * 256];
        float* stile = (float*)sm;             // [256][132]
        mma_epilogue(acc, mbase, nbase, lane, y, bias, relu, bias_div, 0, 0,
                     (float*)0, (unsigned short*)0, stile);
        __syncthreads();
        float* hpart = (float*)(sm + 151552);  // [15][128]
        float s[15];
#pragma unroll
        for (int h = 0; h < 15; h++) s[h] = 0.f;
        int base = role * 128;
        for (int oc = 0; oc < 128; oc++) {
            float v = stile[(base + oc) * 132 + px];
            const float* wr = s_hw + (base + oc) * 16;
#pragma unroll
            for (int h = 0; h < 15; h++)
                if (h < headOC) s[h] += wr[h] * v;
        }
        if (role) {
            for (int h = 0; h < headOC; h++) hpart[h * 128 + px] = s[h];
        }
        __syncthreads();
        if (!role) {
            for (int h = 0; h < headOC; h++)
                hout[(size_t)h * HW + (size_t)y * Ww + px] =
                    hbias[h] + s[h] + hpart[h * 128 + px];
        }
    } else {
        mma_epilogue(acc, mbase, nbase, lane, y, bias, relu, bias_div, writeF, writeP,
                     Yf, Yh, (float*)0);
    }
}

// ---------------- deformable HMMA conv (bilinear gather B), pipelined ----------
#define SMEMD 191488
__global__ void __launch_bounds__(256, 1)
conv_deform_kernel(const unsigned char* __restrict__ wpack,
                   const float* __restrict__ feats, const float* __restrict__ refine,
                   const float* __restrict__ bias, unsigned short* __restrict__ Yh) {
    extern __shared__ unsigned char sm[];
    uint32_t aSm = smem_u32(sm);
    unsigned short* s_idx = (unsigned short*)(sm + 163840);
    float* s_wt = (float*)(sm + 163840 + 9216);

    int tid = threadIdx.x;
    int y = blockIdx.x;
    int lane = tid & 31, wid = tid >> 5;
    int wm = wid >> 1, wn = wid & 1;
    int mbase = wm * 64;
    int half = mbase >> 7;
    int mrow0 = mbase & 127;
    int nbase = wn * 64;
    int lrow = (lane & 7) + ((lane >> 3) & 1) * 8;
    int lcol16 = (lane >> 4) * 16;
    int role = tid >> 7;
    int px = tid & 127;

    for (int e = tid; e < 128 * 9; e += 256) {
        int pxe = e / 9, k = e % 9;
        int p = y * Ww + pxe;
        float axc = refine[p * 5 + 0] * 0.125f;
        float ayc = refine[p * 5 + 1] * 0.125f;
        float aw = refine[p * 5 + 2] * 0.125f;
        float ah = refine[p * 5 + 3] * 0.125f;
        float aa = refine[p * 5 + 4];
        float cs = cosf(aa), sn = sinf(aa);
        float kx = (float)(k % 3 - 1);
        float ky = (float)(k / 3 - 1);
        float ddx = (aw * (1.f / 3.f)) * kx;
        float ddy = (ah * (1.f / 3.f)) * ky;
        float xs = cs * ddx - sn * ddy + axc;
        float ys = sn * ddx + cs * ddy + ayc;
        float x0f = floorf(xs), y0f = floorf(ys);
        float wx1 = xs - x0f, wx0 = 1.f - wx1;
        float wy1 = ys - y0f, wy0 = 1.f - wy1;
        int x0 = (int)x0f, y0 = (int)y0f;
#pragma unroll
        for (int c = 0; c < 4; c++) {
            int xi = x0 + (c & 1);
            int yi = y0 + (c >> 1);
            float ww = ((c & 1) ? wx1 : wx0) * ((c >> 1) ? wy1 : wy0);
            bool valid = (xi >= 0 && xi < Ww && yi >= 0 && yi < Hh);
            int xc = min(max(xi, 0), Ww - 1);
            int yc = min(max(yi, 0), Hh - 1);
            s_idx[(k * 4 + c) * 128 + pxe] = (unsigned short)(yc * Ww + xc);
            s_wt[(k * 4 + c) * 128 + pxe] = valid ? ww : 0.f;
        }
    }

    float acc[4][8][4];
#pragma unroll
    for (int a = 0; a < 4; a++)
#pragma unroll
        for (int b = 0; b < 8; b++)
#pragma unroll
            for (int c = 0; c < 4; c++) acc[a][b][c] = 0.f;

    cp_async_tile(aSm, wpack, tid);
    __syncthreads();

    uint32_t hv[16];
    {
        int tap = 0, ci0 = 0;
        int I0 = s_idx[(tap * 4 + 0) * 128 + px];
        int I1 = s_idx[(tap * 4 + 1) * 128 + px];
        int I2 = s_idx[(tap * 4 + 2) * 128 + px];
        int I3 = s_idx[(tap * 4 + 3) * 128 + px];
        float W0 = s_wt[(tap * 4 + 0) * 128 + px];
        float W1 = s_wt[(tap * 4 + 1) * 128 + px];
        float W2 = s_wt[(tap * 4 + 2) * 128 + px];
        float W3 = s_wt[(tap * 4 + 3) * 128 + px];
        int cbase = ci0 + role * 32;
#pragma unroll
        for (int j = 0; j < 16; j++) {
            const float* f0 = feats + (size_t)(cbase + j * 2) * HW;
            const float* f1 = feats + (size_t)(cbase + j * 2 + 1) * HW;
            float v0 = f0[I0] * W0 + f0[I1] * W1 + f0[I2] * W2 + f0[I3] * W3;
            float v1 = f1[I0] * W0 + f1[I1] * W1 + f1[I2] * W2 + f1[I3] * W3;
            hv[j] = (uint32_t)f16u(v0) | ((uint32_t)f16u(v1) << 16);
        }
    }

    for (int sub = 0; sub < 36; sub++) {
        uint32_t aA = aSm + (uint32_t)(sub & 1) * 65536u;
        uint32_t aB = aSm + 131072u + (uint32_t)(sub & 1) * 16384u;
#pragma unroll
        for (int gg = 0; gg < 4; gg++) {
            uint32_t ofs = (uint32_t)px * 128u +
                           (((uint32_t)(role * 4 + gg) << 4) ^ (((uint32_t)px & 7u) << 4));
            *(uint4*)(sm + (aB - aSm) + ofs) = *(uint4*)&hv[gg * 4];
        }
        cp_async_wait0();
        __syncthreads();
        if (sub + 1 < 36) {
            cp_async_tile(aSm + (uint32_t)((sub + 1) & 1) * 65536u,
                          wpack + (size_t)(sub + 1) * 65536, tid);
            int tap = (sub + 1) >> 2;
            int ci0 = ((sub + 1) & 3) << 6;
            int I0 = s_idx[(tap * 4 + 0) * 128 + px];
            int I1 = s_idx[(tap * 4 + 1) * 128 + px];
            int I2 = s_idx[(tap * 4 + 2) * 128 + px];
            int I3 = s_idx[(tap * 4 + 3) * 128 + px];
            float W0 = s_wt[(tap * 4 + 0) * 128 + px];
            float W1 = s_wt[(tap * 4 + 1) * 128 + px];
            float W2 = s_wt[(tap * 4 + 2) * 128 + px];
            float W3 = s_wt[(tap * 4 + 3) * 128 + px];
            int cbase = ci0 + role * 32;
#pragma unroll
            for (int j = 0; j < 16; j++) {
                const float* f0 = feats + (size_t)(cbase + j * 2) * HW;
                const float* f1 = feats + (size_t)(cbase + j * 2 + 1) * HW;
                float v0 = f0[I0] * W0 + f0[I1] * W1 + f0[I2] * W2 + f0[I3] * W3;
                float v1 = f1[I0] * W0 + f1[I1] * W1 + f1[I2] * W2 + f1[I3] * W3;
                hv[j] = (uint32_t)f16u(v0) | ((uint32_t)f16u(v1) << 16);
            }
        }
        mma_substage(aA, aB, half, mrow0, nbase, lrow, lcol16, acc);
    }

    mma_epilogue(acc, mbase, nbase, lane, y, bias, 1, 1, 0, 1, (float*)0, Yh, (float*)0);
}

// ---------------- head partial conv (one 3x3 tap per block, ODM heads) ----------
__global__ void __launch_bounds__(128, 4)
head_part_kernel(const float* __restrict__ wt, const float* __restrict__ X,
                 float* __restrict__ part, int CI, int NK) {
    __shared__ float Ws[8][16];
    __shared__ float Xs[8][128];

    int y = blockIdx.x;
    int k = blockIdx.y;
    int tid = threadIdx.x;
    int tx = tid & 31;
    int ty = tid >> 5;

    float acc[4][4];
#pragma unroll
    for (int i = 0; i < 4; i++)
#pragma unroll
        for (int j = 0; j < 4; j++) acc[i][j] = 0.f;

    int dy = (NK == 9) ? (k / 3 - 1) : 0;
    int dx = (NK == 9) ? (k % 3 - 1) : 0;
    int yy = y + dy;
    bool rowok = (yy >= 0 && yy < Hh);

    for (int ci0 = 0; ci0 < CI; ci0 += 8) {
        {
            int kk = tid >> 4;
            int m = tid & 15;
            Ws[kk][m] = wt[((size_t)(k * CI + ci0 + kk)) * 16 + m];
        }
        {
            int kk = tid >> 4;
            int lanex = tid & 15;
            const float* xrow = X + (size_t)(ci0 + kk) * HW + yy * Ww;
#pragma unroll
            for (int j = 0; j < 8; j++) {
                int n = lanex + 16 * j;
                int xx = n + dx;
                float v = 0.f;
                if (rowok && xx >= 0 && xx < Ww) v = xrow[xx];
                Xs[kk][n] = v;
            }
        }
        __syncthreads();
#pragma unroll
        for (int kk = 0; kk < 8; kk++) {
            float a[4], b[4];
            *(float4*)a = *(const float4*)&Ws[kk][ty * 4];
            *(float4*)b = *(const float4*)&Xs[kk][tx * 4];
#pragma unroll
            for (int i = 0; i < 4; i++)
#pragma unroll
                for (int j = 0; j < 4; j++) acc[i][j] += a[i] * b[j];
        }
        __syncthreads();
    }

#pragma unroll
    for (int i = 0; i < 4; i++) {
        int m = ty * 4 + i;
#pragma unroll
        for (int j = 0; j < 4; j++) {
            int n = tx * 4 + j;
            part[((size_t)k * 16 + m) * HW + (size_t)y * Ww + n] = acc[i][j];
        }
    }
}

__global__ void head_reduce_kernel(const float* __restrict__ part,
                                   const float* __restrict__ bias,
                                   float* __restrict__ Y, int OC, int NK) {
    int idx = blockIdx.x * blockDim.x + threadIdx.x;
    if (idx >= OC * HW) return;
    int m = idx / HW, p = idx - m * HW;
    float s = bias[m];
    for (int t = 0; t < NK; t++) s += part[((size_t)t * 16 + m) * HW + p];
    Y[(size_t)m * HW + p] = s;
}

// ---------------- anchors + rbox decode ----------------
__global__ void decode_kernel(const float* __restrict__ bbox,
                              float* __restrict__ anchors_out,
                              float* __restrict__ refine_out) {
    int p = blockIdx.x * blockDim.x + threadIdx.x;
    if (p >= HW) return;
    int x = p & 127, yv = p >> 7;
    float ax = x * 8.f + 3.5f;
    float ay = yv * 8.f + 3.5f;
    anchors_out[p * 5 + 0] = ax;
    anchors_out[p * 5 + 1] = ay;
    anchors_out[p * 5 + 2] = 32.f;
    anchors_out[p * 5 + 3] = 32.f;
    anchors_out[p * 5 + 4] = 0.f;

    float dx = bbox[p];
    float dyv = bbox[HW + p];
    float dw = bbox[2 * HW + p];
    float dh = bbox[3 * HW + p];
    float dt = bbox[4 * HW + p];
    const float MR = 13.815510557964274f;
    dw = fminf(fmaxf(dw, -MR), MR);
    dh = fminf(fmaxf(dh, -MR), MR);
    float gx = dx * 32.f + ax;
    float gy = dyv * 32.f + ay;
    float gw = 32.f * expf(dw);
    float gh = 32.f * expf(dh);
    const float PI = 3.14159265358979323846f;
    float r = fmodf(dt + PI * 0.25f, PI);
    if (r < 0.f) r += PI;
    float ga = r - PI * 0.25f;
    refine_out[p * 5 + 0] = gx;
    refine_out[p * 5 + 1] = gy;
    refine_out[p * 5 + 2] = gw;
    refine_out[p * 5 + 3] = gh;
    refine_out[p * 5 + 4] = ga;
}

// ---------------- rotation-invariant max pooling on fp16 pair tensors ----------
__global__ void maxpool8_kernel(const uint32_t* __restrict__ oh,
                                unsigned short* __restrict__ ph) {
    int p = blockIdx.x * blockDim.x + threadIdx.x;
    int i = blockIdx.y;
    if (p >= HW) return;
    float m = -1e30f;
#pragma unroll
    for (int r2 = 0; r2 < 4; r2++) {
        size_t w = (size_t)(i * 4 + r2) * HW + p;
        uint32_t wh = oh[w];
        m = fmaxf(m, fmaxf(half_of(wh, 0), half_of(wh, 1)));
    }
    size_t wo = ((size_t)(i >> 1) * HW + p) * 2 + (i & 1);
    ph[wo] = f16u(m);
}

// ---------------- host orchestration ----------------
extern "C" void kernel_launch(void* const* d_in, const int* in_sizes, int n_in,
                              void* d_out, int out_size) {
    (void)in_sizes; (void)n_in; (void)out_size;

    const float* feats = (const float*)d_in[0];
    const float* fam_reg_w0 = (const float*)d_in[1];
    const float* fam_reg_b0 = (const float*)d_in[2];
    const float* fam_reg_w1 = (const float*)d_in[3];
    const float* fam_reg_b1 = (const float*)d_in[4];
    const float* fam_reg_hw = (const float*)d_in[5];
    const float* fam_reg_hb = (const float*)d_in[6];
    const float* fam_cls_w0 = (const float*)d_in[7];
    const float* fam_cls_b0 = (const float*)d_in[8];
    const float* fam_cls_w1 = (const float*)d_in[9];
    const float* fam_cls_b1 = (const float*)d_in[10];
    const float* fam_cls_hw = (const float*)d_in[11];
    const float* fam_cls_hb = (const float*)d_in[12];
    const float* align_w = (const float*)d_in[13];
    const float* align_b = (const float*)d_in[14];
    const float* or_w = (const float*)d_in[15];
    const float* or_b = (const float*)d_in[16];
    const float* odm_reg_w0 = (const float*)d_in[17];
    const float* odm_reg_b0 = (const float*)d_in[18];
    const float* odm_reg_w1 = (const float*)d_in[19];
    const float* odm_reg_b1 = (const float*)d_in[20];
    const float* odm_reg_hw = (const float*)d_in[21];
    const float* odm_reg_hb = (const float*)d_in[22];
    const float* odm_cls_w0 = (const float*)d_in[23];
    const float* odm_cls_b0 = (const float*)d_in[24];
    const float* odm_cls_w1 = (const float*)d_in[25];
    const float* odm_cls_b1 = (const float*)d_in[26];
    const float* odm_cls_hw = (const float*)d_in[27];
    const float* odm_cls_hb = (const float*)d_in[28];

    float* out = (float*)d_out;
    float* o_famcls = out;
    float* o_fambbox = out + 245760;
    float* o_odmcls = out + 327680;
    float* o_odmbbox = out + 573440;
    float* o_anchors = out + 655360;
    float* o_refine = out + 737280;

    float *b1, *b2, *wts, *hd, *hd2;
    unsigned char* wp;
    uint32_t *p0h, *p1h, *p2h, *p3h, *pdh;
    cudaGetSymbolAddress((void**)&b1, g_b1);
    cudaGetSymbolAddress((void**)&b2, g_b2);
    cudaGetSymbolAddress((void**)&hd, g_head);
    cudaGetSymbolAddress((void**)&hd2, g_head2);
    cudaGetSymbolAddress((void**)&wts, g_wt_small);
    cudaGetSymbolAddress((void**)&wp, g_wpack);
    cudaGetSymbolAddress((void**)&p0h, g_p0h);
    cudaGetSymbolAddress((void**)&p1h, g_p1h);
    cudaGetSymbolAddress((void**)&p2h, g_p2h);
    cudaGetSymbolAddress((void**)&p3h, g_p3h);
    cudaGetSymbolAddress((void**)&pdh, g_pdh);

    cudaFuncSetAttribute(conv_hmma_kernel<0>, cudaFuncAttributeMaxDynamicSharedMemorySize, SMEMH);
    cudaFuncSetAttribute(conv_hmma_kernel<1>, cudaFuncAttributeMaxDynamicSharedMemorySize, SMEMH);
    cudaFuncSetAttribute(conv_deform_kernel, cudaFuncAttributeMaxDynamicSharedMemorySize, SMEMD);

    cudaStream_t s1;
    cudaEvent_t ev0, ev1, ev2, ev3;
    cudaStreamCreateWithFlags(&s1, cudaStreamNonBlocking);
    cudaEventCreateWithFlags(&ev0, cudaEventDisableTiming);
    cudaEventCreateWithFlags(&ev1, cudaEventDisableTiming);
    cudaEventCreateWithFlags(&ev2, cudaEventDisableTiming);
    cudaEventCreateWithFlags(&ev3, cudaEventDisableTiming);

    const size_t SLOT = 36 * 65536;

    // ---- prologue (stream 0) ----
    {
        WPtrs P;
        P.w[0] = fam_reg_w0; P.w[1] = fam_reg_w1; P.w[2] = fam_cls_w0; P.w[3] = fam_cls_w1;
        P.w[4] = align_w; P.w[5] = odm_cls_w1; P.w[6] = odm_reg_w0; P.w[7] = odm_reg_w1;
        P.w[8] = odm_cls_w0;
        repack_all_kernel<<<(8 * 36 * 16384 + 9 * 16384 + 255) / 256, 256>>>(P, wp);
    }
    repack_or_tc_kernel<<<2304, 256>>>(or_w, wp);
    repack_heads_kernel<<<320, 256>>>(fam_reg_hw, fam_cls_hw, odm_cls_hw, odm_reg_hw, wts);
    cvt_pair_kernel<<<8192, 256>>>(feats, p0h, 128 * HW);

    // ---- fork 1: FAM reg (s0) || FAM cls (s1) ----
    cudaEventRecord(ev0, 0);
    cudaStreamWaitEvent(s1, ev0, 0);

    // s0: FAM reg: p0 -> p1; p1 -> fused 1x1 head -> fambbox; decode; deform -> p1
    conv_hmma_kernel<0><<<128, 256, SMEMH>>>(wp + 0 * SLOT, p0h, fam_reg_b0, (float*)0,
                                             (unsigned short*)p1h,
                                             256, 1, 1, 0, 1,
                                             (float*)0, (float*)0, (float*)0, 0);
    conv_hmma_kernel<1><<<128, 256, SMEMH>>>(wp + 1 * SLOT, p1h, fam_reg_b1, (float*)0,
                                             (unsigned short*)0,
                                             256, 1, 1, 0, 0,
                                             wts + 0, fam_reg_hb, o_fambbox, 5);
    decode_kernel<<<HW / 256, 256>>>(o_fambbox, o_anchors, o_refine);
    conv_deform_kernel<<<128, 256, SMEMD>>>(wp + 4 * SLOT, feats, o_refine, align_b,
                                            (unsigned short*)p1h);

    // s1: FAM cls: p0 -> p2; p2 -> fused 1x1 head -> famcls
    conv_hmma_kernel<0><<<128, 256, SMEMH, s1>>>(wp + 2 * SLOT, p0h, fam_cls_b0, (float*)0,
                                                 (unsigned short*)p2h,
                                                 256, 1, 1, 0, 1,
                                                 (float*)0, (float*)0, (float*)0, 0);
    conv_hmma_kernel<1><<<128, 256, SMEMH, s1>>>(wp + 3 * SLOT, p2h, fam_cls_b1, (float*)0,
                                                 (unsigned short*)0,
                                                 256, 1, 1, 0, 0,
                                                 wts + 4096, fam_cls_hb, o_famcls, 15);

    // join 1 (OR overwrites p2, which FAM cls reads)
    cudaEventRecord(ev1, s1);
    cudaStreamWaitEvent(0, ev1, 0);

    // ---- middle (s0): OR conv -> p2, pool -> pd ----
    conv_hmma_kernel<0><<<128, 256, SMEMH>>>(wp + 8 * SLOT, p1h, or_b, (float*)0,
                                             (unsigned short*)p2h,
                                             256, 0, 8, 0, 1,
                                             (float*)0, (float*)0, (float*)0, 0);
    {
        dim3 g(HW / 256, 32);
        maxpool8_kernel<<<g, 256>>>(p2h, (unsigned short*)pdh);
    }

    // ---- fork 2: ODM cls (s0) || ODM reg (s1) ----
    cudaEventRecord(ev2, 0);
    cudaStreamWaitEvent(s1, ev2, 0);

    // s0: ODM cls: pd -> p3, p3 -> b1 fp32, 3x3 head
    conv_hmma_kernel<0><<<128, 256, SMEMH>>>(wp + 9 * SLOT, pdh, odm_cls_b0, (float*)0,
                                             (unsigned short*)p3h,
                                             32, 1, 1, 0, 1,
                                             (float*)0, (float*)0, (float*)0, 0);
    conv_hmma_kernel<0><<<128, 256, SMEMH>>>(wp + 5 * SLOT, p3h, odm_cls_b1, b1,
                                             (unsigned short*)0,
                                             256, 1, 1, 1, 0,
                                             (float*)0, (float*)0, (float*)0, 0);
    head_part_kernel<<<dim3(128, 9), 128>>>(wts + 8192, b1, hd, 256, 9);
    head_reduce_kernel<<<(15 * HW + 255) / 256, 256>>>(hd, odm_cls_hb, o_odmcls, 15, 9);

    // s1: ODM reg: p2 -> p0, p0 -> b2 fp32, 3x3 head
    conv_hmma_kernel<0><<<128, 256, SMEMH, s1>>>(wp + 6 * SLOT, p2h, odm_reg_b0, (float*)0,
                                                 (unsigned short*)p0h,
                                                 256, 1, 1, 0, 1,
                                                 (float*)0, (float*)0, (float*)0, 0);
    conv_hmma_kernel<0><<<128, 256, SMEMH, s1>>>(wp + 7 * SLOT, p0h, odm_reg_b1, b2,
                                                 (unsigned short*)0,
                                                 256, 1, 1, 1, 0,
                                                 (float*)0, (float*)0, (float*)0, 0);
    head_part_kernel<<<dim3(128, 9), 128, 0, s1>>>(wts + 45056, b2, hd2, 256, 9);
    head_reduce_kernel<<<(5 * HW + 255) / 256, 256, 0, s1>>>(hd2, odm_reg_hb, o_odmbbox, 5, 9);

    // join 2
    cudaEventRecord(ev3, s1);
    cudaStreamWaitEvent(0, ev3, 0);
}